// round 1
// baseline (speedup 1.0000x reference)
#include <cuda_runtime.h>
#include <cuda_bf16.h>
#include <math.h>

// ---------------- problem constants ----------------
#define NN        2048      // instances
#define C1OUT     36
#define P1        14        // pooled spatial after conv1
#define P1SZ      (P1*P1)   // 196
#define C2OUT     48
#define C2POS     12        // conv2 valid spatial (12x12)
#define P2        6
#define H0DIM     1728      // 48*6*6
#define HDIM      512
#define H2DIM     1024
#define TDIM      10        // templates
#define NSPLIT    4         // partial-sum splits for embs

// ---------------- scratch (device globals; no runtime alloc) ----------------
__device__ float g_pool1[(size_t)NN * C1OUT * P1SZ];      // [N,36,14,14]
__device__ float g_H0[(size_t)NN * H0DIM];                // conv2 pooled, flattened
__device__ float g_H1[(size_t)NN * HDIM];                 // fc1 out
__device__ float g_H2[(size_t)NN * H2DIM];                // [H | Hn]
__device__ float g_An[(size_t)NN * HDIM];                 // tanh(H W_n^T + b)
__device__ float g_P[(size_t)NN * H2DIM];                 // tanh(H2 Wp^T + b)
__device__ float g_L[(size_t)NN * TDIM];                  // template logits [n][t]
__device__ float g_betas[TDIM * NN];                      // [t][n]
__device__ float g_embs_part[NSPLIT * TDIM * H2DIM];

// ---------------- conv1 + relu + pool (fused) ----------------
__global__ void conv1_kernel(const float* __restrict__ x,
                             const float* __restrict__ w,
                             const float* __restrict__ b) {
    __shared__ float img[1024];   // 32x32
    __shared__ float ws[576];     // 36*16
    __shared__ float bs[36];
    int n = blockIdx.x, tid = threadIdx.x;
    const float* xin = x + (size_t)n * 1024;
    for (int i = tid; i < 1024; i += 256) img[i] = xin[i];
    for (int i = tid; i < 576;  i += 256) ws[i]  = w[i];
    if (tid < 36) bs[tid] = b[tid];
    __syncthreads();

    for (int idx = tid; idx < C1OUT * P1SZ; idx += 256) {
        int ch = idx / P1SZ, p = idx % P1SZ;
        int py = p / P1, px = p % P1;
        int y0 = 2 * py, x0 = 2 * px;

        const float4* wp = (const float4*)&ws[ch * 16];
        float4 w0 = wp[0], w1 = wp[1], w2 = wp[2], w3 = wp[3];
        float wr[16] = {w0.x,w0.y,w0.z,w0.w, w1.x,w1.y,w1.z,w1.w,
                        w2.x,w2.y,w2.z,w2.w, w3.x,w3.y,w3.z,w3.w};
        float im[5][5];
        #pragma unroll
        for (int yy = 0; yy < 5; yy++)
            #pragma unroll
            for (int xx = 0; xx < 5; xx++)
                im[yy][xx] = img[(y0 + yy) * 32 + x0 + xx];

        float m = -3.0e38f;
        #pragma unroll
        for (int dy = 0; dy < 2; dy++)
            #pragma unroll
            for (int dx = 0; dx < 2; dx++) {
                float s = 0.f;
                #pragma unroll
                for (int ky = 0; ky < 4; ky++)
                    #pragma unroll
                    for (int kx = 0; kx < 4; kx++)
                        s += im[dy + ky][dx + kx] * wr[ky * 4 + kx];
                m = fmaxf(m, s);
            }
        g_pool1[(size_t)n * (C1OUT * P1SZ) + idx] = fmaxf(m + bs[ch], 0.f);
    }
}

// ---------------- conv2 + relu + pool (fused), 12-channel chunks ----------------
__global__ void conv2_kernel(const float* __restrict__ w,
                             const float* __restrict__ b) {
    __shared__ float in_s[C1OUT * P1SZ];  // 7056 floats
    __shared__ float wsm[12 * 36 * 9];    // 3888 floats; reused as acc buffer
    int n = blockIdx.x, tid = threadIdx.x;  // 192 threads
    const float* src = g_pool1 + (size_t)n * (C1OUT * P1SZ);
    for (int i = tid; i < C1OUT * P1SZ; i += 192) in_s[i] = src[i];
    int cy = tid / 12, cx = tid % 12;

    for (int cg = 0; cg < 4; cg++) {
        __syncthreads();  // previous pooling reads / in_s load complete
        // load weight chunk: wsm[(c*9+k)*12 + ch] = w[((cg*12+ch)*36+c)*9+k]
        for (int i = tid; i < 3888; i += 192) {
            int ch = i % 12, k = (i / 12) % 9, c = i / 108;
            wsm[i] = w[((cg * 12 + ch) * 36 + c) * 9 + k];
        }
        __syncthreads();

        float acc[12];
        if (tid < 144) {
            #pragma unroll
            for (int t = 0; t < 12; t++) acc[t] = 0.f;
            for (int c = 0; c < 36; c++) {
                float iv[9];
                #pragma unroll
                for (int ky = 0; ky < 3; ky++)
                    #pragma unroll
                    for (int kx = 0; kx < 3; kx++)
                        iv[ky * 3 + kx] = in_s[c * P1SZ + (cy + ky) * P1 + cx + kx];
                const float4* wp = (const float4*)&wsm[c * 108];
                #pragma unroll
                for (int k = 0; k < 9; k++) {
                    float4 wa = wp[k * 3 + 0], wb = wp[k * 3 + 1], wc = wp[k * 3 + 2];
                    float v = iv[k];
                    acc[0] += v * wa.x; acc[1] += v * wa.y; acc[2]  += v * wa.z; acc[3]  += v * wa.w;
                    acc[4] += v * wb.x; acc[5] += v * wb.y; acc[6]  += v * wb.z; acc[7]  += v * wb.w;
                    acc[8] += v * wc.x; acc[9] += v * wc.y; acc[10] += v * wc.z; acc[11] += v * wc.w;
                }
            }
        }
        __syncthreads();
        if (tid < 144) {
            #pragma unroll
            for (int ch = 0; ch < 12; ch++) wsm[tid * 12 + ch] = acc[ch];
        }
        __syncthreads();
        for (int o = tid; o < 432; o += 192) {
            int pp = o / 12, ch = o % 12;
            int py = pp / P2, px = pp % P2;
            int t00 = (2 * py) * 12 + 2 * px;
            float m = fmaxf(fmaxf(wsm[t00 * 12 + ch],        wsm[(t00 + 1)  * 12 + ch]),
                            fmaxf(wsm[(t00 + 12) * 12 + ch], wsm[(t00 + 13) * 12 + ch]));
            int chg = cg * 12 + ch;
            g_H0[(size_t)n * H0DIM + chg * 36 + pp] = fmaxf(m + b[chg], 0.f);
        }
    }
}

// ---------------- generic SGEMM: C = act(A[M,K] @ B[N,K]^T + bias) ----------------
// ACT: 0 none, 1 relu, 2 tanh. 64x64 tile, K-step 16, 256 threads, 4x4/thread.
template <int ACT>
__global__ void sgemm64(const float* __restrict__ A, const float* __restrict__ B,
                        const float* __restrict__ bias, float* __restrict__ C,
                        int K, int lda, int ldb, int ldc) {
    __shared__ float As[16][64];
    __shared__ float Bs[16][64];
    int tid = threadIdx.x;
    int tx = tid & 15, ty = tid >> 4;
    int bm = blockIdx.y * 64, bn = blockIdx.x * 64;
    int lm = tid >> 2, lk = (tid & 3) * 4;   // load mapping: row, k-quad

    float acc[4][4];
    #pragma unroll
    for (int i = 0; i < 4; i++)
        #pragma unroll
        for (int j = 0; j < 4; j++) acc[i][j] = 0.f;

    for (int k0 = 0; k0 < K; k0 += 16) {
        float4 a4 = *(const float4*)(A + (size_t)(bm + lm) * lda + k0 + lk);
        float4 b4 = *(const float4*)(B + (size_t)(bn + lm) * ldb + k0 + lk);
        As[lk + 0][lm] = a4.x; As[lk + 1][lm] = a4.y; As[lk + 2][lm] = a4.z; As[lk + 3][lm] = a4.w;
        Bs[lk + 0][lm] = b4.x; Bs[lk + 1][lm] = b4.y; Bs[lk + 2][lm] = b4.z; Bs[lk + 3][lm] = b4.w;
        __syncthreads();
        #pragma unroll
        for (int k = 0; k < 16; k++) {
            float4 av = *(const float4*)&As[k][ty * 4];
            float4 bv = *(const float4*)&Bs[k][tx * 4];
            float aa[4] = {av.x, av.y, av.z, av.w};
            float bb[4] = {bv.x, bv.y, bv.z, bv.w};
            #pragma unroll
            for (int i = 0; i < 4; i++)
                #pragma unroll
                for (int j = 0; j < 4; j++)
                    acc[i][j] += aa[i] * bb[j];
        }
        __syncthreads();
    }
    #pragma unroll
    for (int i = 0; i < 4; i++) {
        int row = bm + ty * 4 + i;
        #pragma unroll
        for (int j = 0; j < 4; j++) {
            int col = bn + tx * 4 + j;
            float v = acc[i][j] + bias[col];
            if (ACT == 1) v = fmaxf(v, 0.f);
            if (ACT == 2) v = tanhf(v);
            C[(size_t)row * ldc + col] = v;
        }
    }
}

// ---------------- neighborhood attention (one warp per node) ----------------
__global__ void nbr_kernel() {
    int gwarp = (blockIdx.x * blockDim.x + threadIdx.x) >> 5;
    int lane = threadIdx.x & 31;
    if (gwarp >= NN) return;
    int i = gwarp;
    int r = i >> 6, c = i & 63;

    float hi[16];
    const float* Hi = g_H2 + (size_t)i * H2DIM;
    #pragma unroll
    for (int u = 0; u < 16; u++) hi[u] = Hi[lane + 32 * u];

    int nbrs[8]; int cnt = 0;
    for (int dr = -1; dr <= 1; dr++)
        for (int dc = -1; dc <= 1; dc++) {
            if (dr == 0 && dc == 0) continue;
            int rr = r + dr, cc = c + dc;
            if (rr >= 0 && rr < 32 && cc >= 0 && cc < 64) nbrs[cnt++] = rr * 64 + cc;
        }

    float dots[8];
    for (int q = 0; q < cnt; q++) {
        const float* An = g_An + (size_t)nbrs[q] * HDIM;
        float s = 0.f;
        #pragma unroll
        for (int u = 0; u < 16; u++) s += hi[u] * An[lane + 32 * u];
        #pragma unroll
        for (int o = 16; o; o >>= 1) s += __shfl_xor_sync(0xffffffffu, s, o);
        dots[q] = s;
    }
    float m = -3.0e38f;
    for (int q = 0; q < cnt; q++) m = fmaxf(m, dots[q]);
    float ssum = 0.f;
    for (int q = 0; q < cnt; q++) { dots[q] = expf(dots[q] - m); ssum += dots[q]; }
    float inv = 1.f / ssum;

    float accv[16];
    #pragma unroll
    for (int u = 0; u < 16; u++) accv[u] = 0.f;
    for (int q = 0; q < cnt; q++) {
        float a = dots[q] * inv;
        const float* Hj = g_H2 + (size_t)nbrs[q] * H2DIM;
        #pragma unroll
        for (int u = 0; u < 16; u++) accv[u] += a * Hj[lane + 32 * u];
    }
    float* o = g_H2 + (size_t)i * H2DIM + HDIM;
    #pragma unroll
    for (int u = 0; u < 16; u++) o[lane + 32 * u] = accv[u];
}

// ---------------- template logits: L[n][t] = P[n] . templates[t] ----------------
__global__ void tlogits_kernel(const float* __restrict__ templates) {
    int n = blockIdx.x;
    int t = threadIdx.x >> 5, lane = threadIdx.x & 31;  // 320 threads = 10 warps
    const float* p = g_P + (size_t)n * H2DIM;
    const float* tm = templates + (size_t)t * H2DIM;
    float s = 0.f;
    for (int k = lane; k < H2DIM; k += 32) s += p[k] * tm[k];
    #pragma unroll
    for (int o = 16; o; o >>= 1) s += __shfl_xor_sync(0xffffffffu, s, o);
    if (lane == 0) g_L[(size_t)n * TDIM + t] = s;
}

// ---------------- betas: softmax over n for each template ----------------
__global__ void betas_kernel() {
    int t = blockIdx.x, tid = threadIdx.x;  // 256 threads
    __shared__ float red[256];
    __shared__ float smax, ssum;
    float m = -3.0e38f;
    for (int n = tid; n < NN; n += 256) m = fmaxf(m, g_L[(size_t)n * TDIM + t]);
    red[tid] = m; __syncthreads();
    for (int s = 128; s; s >>= 1) { if (tid < s) red[tid] = fmaxf(red[tid], red[tid + s]); __syncthreads(); }
    if (tid == 0) smax = red[0];
    __syncthreads();
    float acc = 0.f;
    for (int n = tid; n < NN; n += 256) acc += expf(g_L[(size_t)n * TDIM + t] - smax);
    red[tid] = acc; __syncthreads();
    for (int s = 128; s; s >>= 1) { if (tid < s) red[tid] += red[tid + s]; __syncthreads(); }
    if (tid == 0) ssum = 1.f / red[0];
    __syncthreads();
    for (int n = tid; n < NN; n += 256)
        g_betas[t * NN + n] = expf(g_L[(size_t)n * TDIM + t] - smax) * ssum;
}

// ---------------- embs partial sums: embs[t] = betas[t] @ H2 ----------------
__global__ void embs_part_kernel() {
    __shared__ float bsh[TDIM * 512];
    int col = blockIdx.x * 128 + threadIdx.x;
    int s = blockIdx.y;
    int n0 = s * 512;
    for (int i = threadIdx.x; i < TDIM * 512; i += 128) {
        int t = i / 512, nl = i % 512;
        bsh[i] = g_betas[t * NN + n0 + nl];
    }
    __syncthreads();
    float acc[TDIM];
    #pragma unroll
    for (int t = 0; t < TDIM; t++) acc[t] = 0.f;
    for (int nl = 0; nl < 512; nl++) {
        float h = g_H2[(size_t)(n0 + nl) * H2DIM + col];
        #pragma unroll
        for (int t = 0; t < TDIM; t++) acc[t] += bsh[t * 512 + nl] * h;
    }
    #pragma unroll
    for (int t = 0; t < TDIM; t++)
        g_embs_part[(size_t)(s * TDIM + t) * H2DIM + col] = acc[t];
}

// ---------------- final: global attention, classifier, A ----------------
__global__ void final_kernel(const float* __restrict__ glob_w1, const float* __restrict__ glob_b1,
                             const float* __restrict__ glob_w2, const float* __restrict__ glob_b2,
                             const float* __restrict__ cls_w,  const float* __restrict__ cls_b,
                             float* __restrict__ out, int out_size) {
    __shared__ float esh[TDIM * H2DIM];   // 40KB
    __shared__ float vsh[1280];           // also reused as M[1024]
    __shared__ float gam[TDIM];
    __shared__ float psh[2];
    int tid = threadIdx.x;  // 256

    // 1) reduce embs partials
    for (int i = tid; i < TDIM * H2DIM; i += 256) {
        float s = 0.f;
        #pragma unroll
        for (int p = 0; p < NSPLIT; p++) s += g_embs_part[(size_t)p * TDIM * H2DIM + i];
        esh[i] = s;
    }
    __syncthreads();

    // 2) v[t][j] = tanh(glob_w1[j] . embs[t] + b1[j])
    for (int idx = tid; idx < TDIM * 128; idx += 256) {
        int t = idx >> 7, j = idx & 127;
        const float* w = glob_w1 + (size_t)j * H2DIM;
        const float* e = esh + t * H2DIM;
        float s = glob_b1[j];
        for (int k = 0; k < H2DIM; k++) s += w[k] * e[k];
        vsh[idx] = tanhf(s);
    }
    __syncthreads();

    // 3) g[t] then gammas softmax
    if (tid < TDIM) {
        float s = glob_b2[0];
        for (int j = 0; j < 128; j++) s += glob_w2[j] * vsh[tid * 128 + j];
        gam[tid] = s;
    }
    __syncthreads();
    if (tid == 0) {
        float m = gam[0];
        for (int t = 1; t < TDIM; t++) m = fmaxf(m, gam[t]);
        float ss = 0.f;
        for (int t = 0; t < TDIM; t++) { gam[t] = expf(gam[t] - m); ss += gam[t]; }
        float inv = 1.f / ss;
        for (int t = 0; t < TDIM; t++) gam[t] *= inv;
    }
    __syncthreads();

    // 5) M[k] = sum_t gam[t]*embs[t][k]   (reuse vsh as M)
    float* Msh = vsh;
    for (int k = tid; k < H2DIM; k += 256) {
        float s = 0.f;
        #pragma unroll
        for (int t = 0; t < TDIM; t++) s += gam[t] * esh[t * H2DIM + k];
        Msh[k] = s;
    }
    __syncthreads();

    // 6) classifier + sigmoid
    if (tid < 64) {
        int c = tid >> 5, lane = tid & 31;
        float s = 0.f;
        for (int k = lane; k < H2DIM; k += 32) s += cls_w[(size_t)c * H2DIM + k] * Msh[k];
        #pragma unroll
        for (int o = 16; o; o >>= 1) s += __shfl_xor_sync(0xffffffffu, s, o);
        if (lane == 0) {
            float p = 1.f / (1.f + expf(-(s + cls_b[c])));
            psh[c] = p;
            if (c < out_size) out[c] = p;
        }
    }
    __syncthreads();
    if (tid == 0 && out_size > 2) out[2] = (psh[1] > psh[0]) ? 1.0f : 0.0f;

    // 8) A[n] = sum_t gam[t]*betas[t][n]
    for (int n = tid; n < NN; n += 256) {
        float s = 0.f;
        #pragma unroll
        for (int t = 0; t < TDIM; t++) s += gam[t] * g_betas[t * NN + n];
        if (3 + n < out_size) out[3 + n] = s;
    }
}

// ---------------- launch ----------------
extern "C" void kernel_launch(void* const* d_in, const int* in_sizes, int n_in,
                              void* d_out, int out_size) {
    const float* x        = (const float*)d_in[0];
    // d_in[1] = positions (int32), recomputed analytically in-kernel
    const float* conv1_w  = (const float*)d_in[2];
    const float* conv1_b  = (const float*)d_in[3];
    const float* conv2_w  = (const float*)d_in[4];
    const float* conv2_b  = (const float*)d_in[5];
    const float* fc1_w    = (const float*)d_in[6];
    const float* fc1_b    = (const float*)d_in[7];
    const float* fc2_w    = (const float*)d_in[8];
    const float* fc2_b    = (const float*)d_in[9];
    const float* nbr_w    = (const float*)d_in[10];
    const float* nbr_b    = (const float*)d_in[11];
    const float* templates= (const float*)d_in[12];
    const float* proto_w  = (const float*)d_in[13];
    const float* proto_b  = (const float*)d_in[14];
    const float* glob_w1  = (const float*)d_in[15];
    const float* glob_b1  = (const float*)d_in[16];
    const float* glob_w2  = (const float*)d_in[17];
    const float* glob_b2  = (const float*)d_in[18];
    const float* cls_w    = (const float*)d_in[19];
    const float* cls_b    = (const float*)d_in[20];
    float* out = (float*)d_out;

    float* H0 = nullptr; float* H1 = nullptr; float* H2 = nullptr;
    float* An = nullptr; float* P  = nullptr;
    cudaGetSymbolAddress((void**)&H0, g_H0);
    cudaGetSymbolAddress((void**)&H1, g_H1);
    cudaGetSymbolAddress((void**)&H2, g_H2);
    cudaGetSymbolAddress((void**)&An, g_An);
    cudaGetSymbolAddress((void**)&P,  g_P);

    conv1_kernel<<<NN, 256>>>(x, conv1_w, conv1_b);
    conv2_kernel<<<NN, 192>>>(conv2_w, conv2_b);

    // fc1: [2048,1728] x [512,1728]^T -> H1, relu
    sgemm64<1><<<dim3(HDIM / 64, NN / 64), 256>>>(H0, fc1_w, fc1_b, H1, H0DIM, H0DIM, H0DIM, HDIM);
    // fc2: -> H2[:, :512], relu (ldc = 1024)
    sgemm64<1><<<dim3(HDIM / 64, NN / 64), 256>>>(H1, fc2_w, fc2_b, H2, HDIM, HDIM, HDIM, H2DIM);
    // An = tanh(H @ nbr_w^T + b)  (A = H2 first 512 cols, lda = 1024)
    sgemm64<2><<<dim3(HDIM / 64, NN / 64), 256>>>(H2, nbr_w, nbr_b, An, HDIM, H2DIM, HDIM, HDIM);
    // neighborhood attention -> H2[:, 512:]
    nbr_kernel<<<NN / 8, 256>>>();
    // P = tanh(H2 @ proto_w^T + b)
    sgemm64<2><<<dim3(H2DIM / 64, NN / 64), 256>>>(H2, proto_w, proto_b, P, H2DIM, H2DIM, H2DIM, H2DIM);

    tlogits_kernel<<<NN, 320>>>(templates);
    betas_kernel<<<TDIM, 256>>>();
    embs_part_kernel<<<dim3(H2DIM / 128, NSPLIT), 128>>>();
    final_kernel<<<1, 256>>>(glob_w1, glob_b1, glob_w2, glob_b2, cls_w, cls_b, out, out_size);
}

// round 2
// speedup vs baseline: 1.0616x; 1.0616x over previous
#include <cuda_runtime.h>
#include <cuda_bf16.h>
#include <math.h>

// ---------------- problem constants ----------------
#define NN        2048      // instances
#define C1OUT     36
#define P1        14        // pooled spatial after conv1
#define P1SZ      (P1*P1)   // 196
#define C2OUT     48
#define P2        6
#define H0DIM     1728      // 48*6*6
#define HDIM      512
#define H2DIM     1024
#define TDIM      10        // templates
#define NSPLIT    4         // partial-sum splits for embs

// SMEM layout (floats) for fused conv kernel
#define S_IMG     0                      // 32 x 33 (padded) = 1056
#define S_W1      1056                   // 36*16 = 576
#define S_B1      1632                   // 36
#define S_B2      1668                   // 48
#define S_POOL1   1716                   // 36*196 = 7056
#define S_W2      8772                   // 324*48 = 15552 ; reused (stride 49) as conv2 out
#define S_TOTALF  (8772 + 15552)         // 24324 floats = 97296 B

// ---------------- scratch (device globals; no runtime alloc) ----------------
__device__ float g_H0[(size_t)NN * H0DIM];                // conv2 pooled, flattened
__device__ float g_H1[(size_t)NN * HDIM];                 // fc1 out
__device__ float g_H2[(size_t)NN * H2DIM];                // [H | Hn]
__device__ float g_An[(size_t)NN * HDIM];                 // tanh(H W_n^T + b)
__device__ float g_P[(size_t)NN * H2DIM];                 // tanh(H2 Wp^T + b)
__device__ float g_L[(size_t)NN * TDIM];                  // template logits [n][t]
__device__ float g_betas[TDIM * NN];                      // [t][n]
__device__ float g_embs_part[NSPLIT * TDIM * H2DIM];

// ---------------- fused conv1+pool1+conv2+pool2 (one block per image) ----------------
__global__ __launch_bounds__(512, 2)
void conv_fused_kernel(const float* __restrict__ x,
                       const float* __restrict__ w1,
                       const float* __restrict__ b1,
                       const float* __restrict__ w2,
                       const float* __restrict__ b2) {
    extern __shared__ float sm[];
    float* s_img   = sm + S_IMG;
    float* s_w1    = sm + S_W1;
    float* s_b1    = sm + S_B1;
    float* s_b2    = sm + S_B2;
    float* s_pool1 = sm + S_POOL1;
    float* s_w2    = sm + S_W2;

    int n = blockIdx.x, tid = threadIdx.x;
    const float* xin = x + (size_t)n * 1024;

    // --- cooperative loads ---
    for (int i = tid; i < 1024; i += 512) {
        int r = i >> 5, c = i & 31;
        s_img[r * 33 + c] = xin[i];
    }
    for (int i = tid; i < 576; i += 512) s_w1[i] = w1[i];
    if (tid < 36) s_b1[tid] = b1[tid];
    else if (tid >= 64 && tid < 112) s_b2[tid - 64] = b2[tid - 64];
    // conv2 weights: w2 linear = ch*324 + (c*9+k). SMEM layout: s_w2[(c*9+k)*48 + ch]
    for (int i = tid; i < 15552; i += 512) {
        int ch = i / 324, r = i - ch * 324;
        s_w2[r * 48 + ch] = w2[i];
    }
    __syncthreads();

    // --- conv1 + relu + pool -> s_pool1 ---
    // thread = (ch, py): 36*14 = 504 threads; each computes one pooled row (14 outputs)
    if (tid < 504) {
        int ch = tid / 14, py = tid % 14;
        const float4* wp = (const float4*)&s_w1[ch * 16];
        float4 a0 = wp[0], a1 = wp[1], a2 = wp[2], a3 = wp[3];
        float wr[16] = {a0.x,a0.y,a0.z,a0.w, a1.x,a1.y,a1.z,a1.w,
                        a2.x,a2.y,a2.z,a2.w, a3.x,a3.y,a3.z,a3.w};
        float bias1 = s_b1[ch];
        float* prow = s_pool1 + ch * 196 + py * 14;

        #pragma unroll
        for (int px2 = 0; px2 < 7; px2++) {
            int x0 = 4 * px2;
            float im[5][7];
            #pragma unroll
            for (int yy = 0; yy < 5; yy++)
                #pragma unroll
                for (int xx = 0; xx < 7; xx++)
                    im[yy][xx] = s_img[(2 * py + yy) * 33 + x0 + xx];

            float m0 = -3.0e38f, m1 = -3.0e38f;
            #pragma unroll
            for (int dy = 0; dy < 2; dy++)
                #pragma unroll
                for (int dx = 0; dx < 4; dx++) {
                    float s = 0.f;
                    #pragma unroll
                    for (int ky = 0; ky < 4; ky++)
                        #pragma unroll
                        for (int kx = 0; kx < 4; kx++)
                            s += im[dy + ky][dx + kx] * wr[ky * 4 + kx];
                    if (dx < 2) m0 = fmaxf(m0, s); else m1 = fmaxf(m1, s);
                }
            prow[2 * px2 + 0] = fmaxf(m0 + bias1, 0.f);
            prow[2 * px2 + 1] = fmaxf(m1 + bias1, 0.f);
        }
    }
    __syncthreads();

    // --- conv2: thread = (chgroup g of 16, position p) ; 3*144 = 432 threads ---
    float acc[16];
    int g = tid / 144, p = tid - g * 144;
    if (tid < 432) {
        int cy = p / 12, cx = p - cy * 12;
        #pragma unroll
        for (int j = 0; j < 16; j++) acc[j] = 0.f;
        const float* inb = s_pool1 + cy * 14 + cx;
        for (int c = 0; c < 36; c++) {
            float iv[9];
            #pragma unroll
            for (int ky = 0; ky < 3; ky++)
                #pragma unroll
                for (int kx = 0; kx < 3; kx++)
                    iv[ky * 3 + kx] = inb[c * 196 + ky * 14 + kx];
            const float* wb = s_w2 + c * 432 + g * 16;   // (c*9+k)*48 = c*432 + k*48
            #pragma unroll
            for (int k = 0; k < 9; k++) {
                const float4* q = (const float4*)(wb + k * 48);
                float4 q0 = q[0], q1 = q[1], q2 = q[2], q3 = q[3];
                float v = iv[k];
                acc[0]  += v * q0.x; acc[1]  += v * q0.y; acc[2]  += v * q0.z; acc[3]  += v * q0.w;
                acc[4]  += v * q1.x; acc[5]  += v * q1.y; acc[6]  += v * q1.z; acc[7]  += v * q1.w;
                acc[8]  += v * q2.x; acc[9]  += v * q2.y; acc[10] += v * q2.z; acc[11] += v * q2.w;
                acc[12] += v * q3.x; acc[13] += v * q3.y; acc[14] += v * q3.z; acc[15] += v * q3.w;
            }
        }
    }
    __syncthreads();   // weights no longer needed -> reuse s_w2 as out buffer (stride 49)
    if (tid < 432) {
        float* o = s_w2 + p * 49 + g * 16;
        #pragma unroll
        for (int j = 0; j < 16; j++) o[j] = acc[j];
    }
    __syncthreads();

    // --- pool2 + bias + relu -> g_H0 (coalesced: index = ch*36 + pp) ---
    float* outb = g_H0 + (size_t)n * H0DIM;
    for (int o = tid; o < 1728; o += 512) {
        int ch = o / 36, pp = o - ch * 36;
        int py = pp / 6, px = pp - py * 6;
        int i00 = (2 * py) * 12 + 2 * px;
        float m = fmaxf(fmaxf(s_w2[i00 * 49 + ch],        s_w2[(i00 + 1)  * 49 + ch]),
                        fmaxf(s_w2[(i00 + 12) * 49 + ch], s_w2[(i00 + 13) * 49 + ch]));
        outb[o] = fmaxf(m + s_b2[ch], 0.f);
    }
}

// ---------------- generic SGEMM: C = act(A[M,K] @ B[N,K]^T + bias) ----------------
// ACT: 0 none, 1 relu, 2 tanh. 64x64 tile, K-step 16, 256 threads, 4x4/thread.
template <int ACT>
__global__ void sgemm64(const float* __restrict__ A, const float* __restrict__ B,
                        const float* __restrict__ bias, float* __restrict__ C,
                        int K, int lda, int ldb, int ldc) {
    __shared__ float As[16][64];
    __shared__ float Bs[16][64];
    int tid = threadIdx.x;
    int tx = tid & 15, ty = tid >> 4;
    int bm = blockIdx.y * 64, bn = blockIdx.x * 64;
    int lm = tid >> 2, lk = (tid & 3) * 4;

    float acc[4][4];
    #pragma unroll
    for (int i = 0; i < 4; i++)
        #pragma unroll
        for (int j = 0; j < 4; j++) acc[i][j] = 0.f;

    for (int k0 = 0; k0 < K; k0 += 16) {
        float4 a4 = *(const float4*)(A + (size_t)(bm + lm) * lda + k0 + lk);
        float4 b4 = *(const float4*)(B + (size_t)(bn + lm) * ldb + k0 + lk);
        As[lk + 0][lm] = a4.x; As[lk + 1][lm] = a4.y; As[lk + 2][lm] = a4.z; As[lk + 3][lm] = a4.w;
        Bs[lk + 0][lm] = b4.x; Bs[lk + 1][lm] = b4.y; Bs[lk + 2][lm] = b4.z; Bs[lk + 3][lm] = b4.w;
        __syncthreads();
        #pragma unroll
        for (int k = 0; k < 16; k++) {
            float4 av = *(const float4*)&As[k][ty * 4];
            float4 bv = *(const float4*)&Bs[k][tx * 4];
            float aa[4] = {av.x, av.y, av.z, av.w};
            float bb[4] = {bv.x, bv.y, bv.z, bv.w};
            #pragma unroll
            for (int i = 0; i < 4; i++)
                #pragma unroll
                for (int j = 0; j < 4; j++)
                    acc[i][j] += aa[i] * bb[j];
        }
        __syncthreads();
    }
    #pragma unroll
    for (int i = 0; i < 4; i++) {
        int row = bm + ty * 4 + i;
        #pragma unroll
        for (int j = 0; j < 4; j++) {
            int col = bn + tx * 4 + j;
            float v = acc[i][j] + bias[col];
            if (ACT == 1) v = fmaxf(v, 0.f);
            if (ACT == 2) v = tanhf(v);
            C[(size_t)row * ldc + col] = v;
        }
    }
}

// ---------------- neighborhood attention (one warp per node) ----------------
__global__ void nbr_kernel() {
    int gwarp = (blockIdx.x * blockDim.x + threadIdx.x) >> 5;
    int lane = threadIdx.x & 31;
    if (gwarp >= NN) return;
    int i = gwarp;
    int r = i >> 6, c = i & 63;

    float hi[16];
    const float* Hi = g_H2 + (size_t)i * H2DIM;
    #pragma unroll
    for (int u = 0; u < 16; u++) hi[u] = Hi[lane + 32 * u];

    int nbrs[8]; int cnt = 0;
    for (int dr = -1; dr <= 1; dr++)
        for (int dc = -1; dc <= 1; dc++) {
            if (dr == 0 && dc == 0) continue;
            int rr = r + dr, cc = c + dc;
            if (rr >= 0 && rr < 32 && cc >= 0 && cc < 64) nbrs[cnt++] = rr * 64 + cc;
        }

    float dots[8];
    for (int q = 0; q < cnt; q++) {
        const float* An = g_An + (size_t)nbrs[q] * HDIM;
        float s = 0.f;
        #pragma unroll
        for (int u = 0; u < 16; u++) s += hi[u] * An[lane + 32 * u];
        #pragma unroll
        for (int o = 16; o; o >>= 1) s += __shfl_xor_sync(0xffffffffu, s, o);
        dots[q] = s;
    }
    float m = -3.0e38f;
    for (int q = 0; q < cnt; q++) m = fmaxf(m, dots[q]);
    float ssum = 0.f;
    for (int q = 0; q < cnt; q++) { dots[q] = expf(dots[q] - m); ssum += dots[q]; }
    float inv = 1.f / ssum;

    float accv[16];
    #pragma unroll
    for (int u = 0; u < 16; u++) accv[u] = 0.f;
    for (int q = 0; q < cnt; q++) {
        float a = dots[q] * inv;
        const float* Hj = g_H2 + (size_t)nbrs[q] * H2DIM;
        #pragma unroll
        for (int u = 0; u < 16; u++) accv[u] += a * Hj[lane + 32 * u];
    }
    float* o = g_H2 + (size_t)i * H2DIM + HDIM;
    #pragma unroll
    for (int u = 0; u < 16; u++) o[lane + 32 * u] = accv[u];
}

// ---------------- template logits: L[n][t] = P[n] . templates[t] ----------------
__global__ void tlogits_kernel(const float* __restrict__ templates) {
    int n = blockIdx.x;
    int t = threadIdx.x >> 5, lane = threadIdx.x & 31;  // 320 threads = 10 warps
    const float* p = g_P + (size_t)n * H2DIM;
    const float* tm = templates + (size_t)t * H2DIM;
    float s = 0.f;
    for (int k = lane; k < H2DIM; k += 32) s += p[k] * tm[k];
    #pragma unroll
    for (int o = 16; o; o >>= 1) s += __shfl_xor_sync(0xffffffffu, s, o);
    if (lane == 0) g_L[(size_t)n * TDIM + t] = s;
}

// ---------------- betas: softmax over n for each template ----------------
__global__ void betas_kernel() {
    int t = blockIdx.x, tid = threadIdx.x;  // 256 threads
    __shared__ float red[256];
    __shared__ float smax, ssum;
    float m = -3.0e38f;
    for (int n = tid; n < NN; n += 256) m = fmaxf(m, g_L[(size_t)n * TDIM + t]);
    red[tid] = m; __syncthreads();
    for (int s = 128; s; s >>= 1) { if (tid < s) red[tid] = fmaxf(red[tid], red[tid + s]); __syncthreads(); }
    if (tid == 0) smax = red[0];
    __syncthreads();
    float acc = 0.f;
    for (int n = tid; n < NN; n += 256) acc += expf(g_L[(size_t)n * TDIM + t] - smax);
    red[tid] = acc; __syncthreads();
    for (int s = 128; s; s >>= 1) { if (tid < s) red[tid] += red[tid + s]; __syncthreads(); }
    if (tid == 0) ssum = 1.f / red[0];
    __syncthreads();
    for (int n = tid; n < NN; n += 256)
        g_betas[t * NN + n] = expf(g_L[(size_t)n * TDIM + t] - smax) * ssum;
}

// ---------------- embs partial sums: embs[t] = betas[t] @ H2 ----------------
__global__ void embs_part_kernel() {
    __shared__ float bsh[TDIM * 512];
    int col = blockIdx.x * 128 + threadIdx.x;
    int s = blockIdx.y;
    int n0 = s * 512;
    for (int i = threadIdx.x; i < TDIM * 512; i += 128) {
        int t = i / 512, nl = i % 512;
        bsh[i] = g_betas[t * NN + n0 + nl];
    }
    __syncthreads();
    float acc[TDIM];
    #pragma unroll
    for (int t = 0; t < TDIM; t++) acc[t] = 0.f;
    for (int nl = 0; nl < 512; nl++) {
        float h = g_H2[(size_t)(n0 + nl) * H2DIM + col];
        #pragma unroll
        for (int t = 0; t < TDIM; t++) acc[t] += bsh[t * 512 + nl] * h;
    }
    #pragma unroll
    for (int t = 0; t < TDIM; t++)
        g_embs_part[(size_t)(s * TDIM + t) * H2DIM + col] = acc[t];
}

// ---------------- final: global attention, classifier, A ----------------
__global__ void final_kernel(const float* __restrict__ glob_w1, const float* __restrict__ glob_b1,
                             const float* __restrict__ glob_w2, const float* __restrict__ glob_b2,
                             const float* __restrict__ cls_w,  const float* __restrict__ cls_b,
                             float* __restrict__ out, int out_size) {
    __shared__ float esh[TDIM * H2DIM];   // 40KB
    __shared__ float vsh[1280];           // also reused as M[1024]
    __shared__ float gam[TDIM];
    __shared__ float psh[2];
    int tid = threadIdx.x;  // 256

    for (int i = tid; i < TDIM * H2DIM; i += 256) {
        float s = 0.f;
        #pragma unroll
        for (int p = 0; p < NSPLIT; p++) s += g_embs_part[(size_t)p * TDIM * H2DIM + i];
        esh[i] = s;
    }
    __syncthreads();

    for (int idx = tid; idx < TDIM * 128; idx += 256) {
        int t = idx >> 7, j = idx & 127;
        const float* w = glob_w1 + (size_t)j * H2DIM;
        const float* e = esh + t * H2DIM;
        float s = glob_b1[j];
        for (int k = 0; k < H2DIM; k++) s += w[k] * e[k];
        vsh[idx] = tanhf(s);
    }
    __syncthreads();

    if (tid < TDIM) {
        float s = glob_b2[0];
        for (int j = 0; j < 128; j++) s += glob_w2[j] * vsh[tid * 128 + j];
        gam[tid] = s;
    }
    __syncthreads();
    if (tid == 0) {
        float m = gam[0];
        for (int t = 1; t < TDIM; t++) m = fmaxf(m, gam[t]);
        float ss = 0.f;
        for (int t = 0; t < TDIM; t++) { gam[t] = expf(gam[t] - m); ss += gam[t]; }
        float inv = 1.f / ss;
        for (int t = 0; t < TDIM; t++) gam[t] *= inv;
    }
    __syncthreads();

    float* Msh = vsh;
    for (int k = tid; k < H2DIM; k += 256) {
        float s = 0.f;
        #pragma unroll
        for (int t = 0; t < TDIM; t++) s += gam[t] * esh[t * H2DIM + k];
        Msh[k] = s;
    }
    __syncthreads();

    if (tid < 64) {
        int c = tid >> 5, lane = tid & 31;
        float s = 0.f;
        for (int k = lane; k < H2DIM; k += 32) s += cls_w[(size_t)c * H2DIM + k] * Msh[k];
        #pragma unroll
        for (int o = 16; o; o >>= 1) s += __shfl_xor_sync(0xffffffffu, s, o);
        if (lane == 0) {
            float p = 1.f / (1.f + expf(-(s + cls_b[c])));
            psh[c] = p;
            if (c < out_size) out[c] = p;
        }
    }
    __syncthreads();
    if (tid == 0 && out_size > 2) out[2] = (psh[1] > psh[0]) ? 1.0f : 0.0f;

    for (int n = tid; n < NN; n += 256) {
        float s = 0.f;
        #pragma unroll
        for (int t = 0; t < TDIM; t++) s += gam[t] * g_betas[t * NN + n];
        if (3 + n < out_size) out[3 + n] = s;
    }
}

// ---------------- launch ----------------
extern "C" void kernel_launch(void* const* d_in, const int* in_sizes, int n_in,
                              void* d_out, int out_size) {
    const float* x        = (const float*)d_in[0];
    const float* conv1_w  = (const float*)d_in[2];
    const float* conv1_b  = (const float*)d_in[3];
    const float* conv2_w  = (const float*)d_in[4];
    const float* conv2_b  = (const float*)d_in[5];
    const float* fc1_w    = (const float*)d_in[6];
    const float* fc1_b    = (const float*)d_in[7];
    const float* fc2_w    = (const float*)d_in[8];
    const float* fc2_b    = (const float*)d_in[9];
    const float* nbr_w    = (const float*)d_in[10];
    const float* nbr_b    = (const float*)d_in[11];
    const float* templates= (const float*)d_in[12];
    const float* proto_w  = (const float*)d_in[13];
    const float* proto_b  = (const float*)d_in[14];
    const float* glob_w1  = (const float*)d_in[15];
    const float* glob_b1  = (const float*)d_in[16];
    const float* glob_w2  = (const float*)d_in[17];
    const float* glob_b2  = (const float*)d_in[18];
    const float* cls_w    = (const float*)d_in[19];
    const float* cls_b    = (const float*)d_in[20];
    float* out = (float*)d_out;

    float* H0 = nullptr; float* H1 = nullptr; float* H2 = nullptr;
    float* An = nullptr; float* P  = nullptr;
    cudaGetSymbolAddress((void**)&H0, g_H0);
    cudaGetSymbolAddress((void**)&H1, g_H1);
    cudaGetSymbolAddress((void**)&H2, g_H2);
    cudaGetSymbolAddress((void**)&An, g_An);
    cudaGetSymbolAddress((void**)&P,  g_P);

    static const size_t conv_smem = S_TOTALF * sizeof(float);
    cudaFuncSetAttribute(conv_fused_kernel, cudaFuncAttributeMaxDynamicSharedMemorySize, (int)conv_smem);

    conv_fused_kernel<<<NN, 512, conv_smem>>>(x, conv1_w, conv1_b, conv2_w, conv2_b);

    // fc1: [2048,1728] x [512,1728]^T -> H1, relu
    sgemm64<1><<<dim3(HDIM / 64, NN / 64), 256>>>(H0, fc1_w, fc1_b, H1, H0DIM, H0DIM, H0DIM, HDIM);
    // fc2: -> H2[:, :512], relu (ldc = 1024)
    sgemm64<1><<<dim3(HDIM / 64, NN / 64), 256>>>(H1, fc2_w, fc2_b, H2, HDIM, HDIM, HDIM, H2DIM);
    // An = tanh(H @ nbr_w^T + b)  (A = H2 first 512 cols, lda = 1024)
    sgemm64<2><<<dim3(HDIM / 64, NN / 64), 256>>>(H2, nbr_w, nbr_b, An, HDIM, H2DIM, HDIM, HDIM);
    // neighborhood attention -> H2[:, 512:]
    nbr_kernel<<<NN / 8, 256>>>();
    // P = tanh(H2 @ proto_w^T + b)
    sgemm64<2><<<dim3(H2DIM / 64, NN / 64), 256>>>(H2, proto_w, proto_b, P, H2DIM, H2DIM, H2DIM, H2DIM);

    tlogits_kernel<<<NN, 320>>>(templates);
    betas_kernel<<<TDIM, 256>>>();
    embs_part_kernel<<<dim3(H2DIM / 128, NSPLIT), 128>>>();
    final_kernel<<<1, 256>>>(glob_w1, glob_b1, glob_w2, glob_b2, cls_w, cls_b, out, out_size);
}

// round 3
// speedup vs baseline: 1.0858x; 1.0227x over previous
#include <cuda_runtime.h>
#include <cuda_bf16.h>
#include <math.h>

typedef unsigned long long ull;

// ---------------- packed f32x2 helpers (sm_100a FFMA2) ----------------
__device__ __forceinline__ ull pack2(float lo, float hi) {
    ull r; asm("mov.b64 %0, {%1, %2};" : "=l"(r) : "f"(lo), "f"(hi)); return r;
}
__device__ __forceinline__ void unpack2(ull v, float& lo, float& hi) {
    asm("mov.b64 {%0, %1}, %2;" : "=f"(lo), "=f"(hi) : "l"(v));
}
__device__ __forceinline__ void fma2(ull& d, ull a, ull b) {
    asm("fma.rn.f32x2 %0, %1, %2, %0;" : "+l"(d) : "l"(a), "l"(b));
}

// ---------------- problem constants ----------------
#define NN        2048
#define C1OUT     36
#define P1        14
#define P1SZ      (P1*P1)   // 196
#define H0DIM     1728
#define HDIM      512
#define H2DIM     1024
#define TDIM      10
#define NSPLIT    4

// SMEM layout (floats) for fused conv kernel
#define S_IMG     0                      // 32 x 33 padded = 1056
#define S_W1      1056                   // 576
#define S_B1      1632                   // 36
#define S_B2      1668                   // 48
#define S_POOL1   1716                   // 7056
#define S_W2      8772                   // 15552 ; reused (stride 49) as conv2 out
#define S_TOTALF  (8772 + 15552)         // 97296 B

// ---------------- scratch ----------------
__device__ float g_H0[(size_t)NN * H0DIM];
__device__ float g_H1[(size_t)NN * HDIM];
__device__ float g_H2[(size_t)NN * H2DIM];
__device__ float g_An[(size_t)NN * HDIM];
__device__ float g_P[(size_t)NN * H2DIM];
__device__ float g_L[(size_t)NN * TDIM];
__device__ float g_betas[TDIM * NN];
__device__ float g_embs_part[NSPLIT * TDIM * H2DIM];

// ---------------- profiling alignment no-op ----------------
__global__ void noop_kernel() {}

// ---------------- fused conv1+pool1+conv2+pool2 ----------------
__global__ __launch_bounds__(512, 2)
void conv_fused_kernel(const float* __restrict__ x,
                       const float* __restrict__ w1,
                       const float* __restrict__ b1,
                       const float* __restrict__ w2,
                       const float* __restrict__ b2) {
    extern __shared__ float sm[];
    float* s_img   = sm + S_IMG;
    float* s_w1    = sm + S_W1;
    float* s_b1    = sm + S_B1;
    float* s_b2    = sm + S_B2;
    float* s_pool1 = sm + S_POOL1;
    float* s_w2    = sm + S_W2;

    int n = blockIdx.x, tid = threadIdx.x;
    const float* xin = x + (size_t)n * 1024;

    for (int i = tid; i < 1024; i += 512) {
        int r = i >> 5, c = i & 31;
        s_img[r * 33 + c] = xin[i];
    }
    for (int i = tid; i < 576; i += 512) s_w1[i] = w1[i];
    if (tid < 36) s_b1[tid] = b1[tid];
    else if (tid >= 64 && tid < 112) s_b2[tid - 64] = b2[tid - 64];
    // conv2 weights: w2 linear = ch*324 + r. SMEM: s_w2[r*48 + ch]
    for (int i = tid; i < 15552; i += 512) {
        int ch = i / 324, r = i - ch * 324;
        s_w2[r * 48 + ch] = w2[i];
    }
    __syncthreads();

    // --- conv1 + relu + pool: thread = (ch, py), loop px ---
    if (tid < 504) {
        int ch = tid / 14, py = tid % 14;
        const float4* wp = (const float4*)&s_w1[ch * 16];
        float4 a0 = wp[0], a1 = wp[1], a2 = wp[2], a3 = wp[3];
        float wr[16] = {a0.x,a0.y,a0.z,a0.w, a1.x,a1.y,a1.z,a1.w,
                        a2.x,a2.y,a2.z,a2.w, a3.x,a3.y,a3.z,a3.w};
        float bias1 = s_b1[ch];
        float* prow = s_pool1 + ch * 196 + py * 14;
        for (int px = 0; px < 14; px++) {
            float im[5][5];
            #pragma unroll
            for (int yy = 0; yy < 5; yy++)
                #pragma unroll
                for (int xx = 0; xx < 5; xx++)
                    im[yy][xx] = s_img[(2 * py + yy) * 33 + 2 * px + xx];
            float m = -3.0e38f;
            #pragma unroll
            for (int dy = 0; dy < 2; dy++)
                #pragma unroll
                for (int dx = 0; dx < 2; dx++) {
                    float s = 0.f;
                    #pragma unroll
                    for (int ky = 0; ky < 4; ky++)
                        #pragma unroll
                        for (int kx = 0; kx < 4; kx++)
                            s += im[dy + ky][dx + kx] * wr[ky * 4 + kx];
                    m = fmaxf(m, s);
                }
            prow[px] = fmaxf(m + bias1, 0.f);
        }
    }
    __syncthreads();

    // --- conv2: thread = (16-ch group g, position p); packed f32x2 acc ---
    ull accp[8];
    int g = tid / 144, p = tid - g * 144;
    if (tid < 432) {
        int cy = p / 12, cx = p - cy * 12;
        #pragma unroll
        for (int j = 0; j < 8; j++) accp[j] = 0ull;
        const float* inb = s_pool1 + cy * 14 + cx;
        const float* wgb = s_w2 + g * 16;
        for (int c = 0; c < 36; c++) {
            #pragma unroll
            for (int k = 0; k < 9; k++) {
                float v = inb[c * 196 + (k / 3) * 14 + (k % 3)];
                ull vv = pack2(v, v);
                const ull* q = (const ull*)(wgb + (c * 9 + k) * 48);
                fma2(accp[0], q[0], vv); fma2(accp[1], q[1], vv);
                fma2(accp[2], q[2], vv); fma2(accp[3], q[3], vv);
                fma2(accp[4], q[4], vv); fma2(accp[5], q[5], vv);
                fma2(accp[6], q[6], vv); fma2(accp[7], q[7], vv);
            }
        }
    }
    __syncthreads();   // weights done -> reuse s_w2 as out buffer (stride 49)
    if (tid < 432) {
        float* o = s_w2 + p * 49 + g * 16;
        #pragma unroll
        for (int j = 0; j < 8; j++) {
            float lo, hi; unpack2(accp[j], lo, hi);
            o[2 * j] = lo; o[2 * j + 1] = hi;
        }
    }
    __syncthreads();

    // --- pool2 + bias + relu -> g_H0 ---
    float* outb = g_H0 + (size_t)n * H0DIM;
    for (int o = tid; o < 1728; o += 512) {
        int ch = o / 36, pp = o - ch * 36;
        int py = pp / 6, px = pp - py * 6;
        int i00 = (2 * py) * 12 + 2 * px;
        float m = fmaxf(fmaxf(s_w2[i00 * 49 + ch],        s_w2[(i00 + 1)  * 49 + ch]),
                        fmaxf(s_w2[(i00 + 12) * 49 + ch], s_w2[(i00 + 13) * 49 + ch]));
        outb[o] = fmaxf(m + s_b2[ch], 0.f);
    }
}

// ---------------- SGEMM v2: C = act(A[M,K] @ B[N,K]^T + bias), FFMA2 ----------------
// 128(M) x 64(N) tile, 256 threads, per-thread 8x4 as 4 M-pairs x 4 N (f32x2).
template <int ACT>
__global__ __launch_bounds__(256)
void sgemm128(const float* __restrict__ A, const float* __restrict__ B,
              const float* __restrict__ bias, float* __restrict__ C,
              int K, int lda, int ldb, int ldc) {
    __shared__ float As[16][128];
    __shared__ float Bs[16][72];   // padded: conflict-free stores
    int tid = threadIdx.x;
    int tx = tid & 15, ty = tid >> 4;
    int bm = blockIdx.y * 128, bn = blockIdx.x * 64;
    int lmA = tid >> 1, lkA = (tid & 1) * 8;
    int lmB = tid >> 2, lkB = (tid & 3) * 4;

    ull acc[4][4];
    #pragma unroll
    for (int i = 0; i < 4; i++)
        #pragma unroll
        for (int j = 0; j < 4; j++) acc[i][j] = 0ull;

    const float* Ag = A + (size_t)(bm + lmA) * lda + lkA;
    const float* Bg = B + (size_t)(bn + lmB) * ldb + lkB;

    for (int k0 = 0; k0 < K; k0 += 16) {
        float4 a0 = *(const float4*)(Ag + k0);
        float4 a1 = *(const float4*)(Ag + k0 + 4);
        float4 b0 = *(const float4*)(Bg + k0);
        As[lkA + 0][lmA] = a0.x; As[lkA + 1][lmA] = a0.y;
        As[lkA + 2][lmA] = a0.z; As[lkA + 3][lmA] = a0.w;
        As[lkA + 4][lmA] = a1.x; As[lkA + 5][lmA] = a1.y;
        As[lkA + 6][lmA] = a1.z; As[lkA + 7][lmA] = a1.w;
        Bs[lkB + 0][lmB] = b0.x; Bs[lkB + 1][lmB] = b0.y;
        Bs[lkB + 2][lmB] = b0.z; Bs[lkB + 3][lmB] = b0.w;
        __syncthreads();
        #pragma unroll
        for (int k = 0; k < 16; k++) {
            const ull* ap = (const ull*)&As[k][ty * 8];   // 4 packed M-pairs
            ull ad0 = ap[0], ad1 = ap[1], ad2 = ap[2], ad3 = ap[3];
            float4 bv = *(const float4*)&Bs[k][tx * 4];
            ull bb0 = pack2(bv.x, bv.x), bb1 = pack2(bv.y, bv.y);
            ull bb2 = pack2(bv.z, bv.z), bb3 = pack2(bv.w, bv.w);
            fma2(acc[0][0], ad0, bb0); fma2(acc[0][1], ad0, bb1);
            fma2(acc[0][2], ad0, bb2); fma2(acc[0][3], ad0, bb3);
            fma2(acc[1][0], ad1, bb0); fma2(acc[1][1], ad1, bb1);
            fma2(acc[1][2], ad1, bb2); fma2(acc[1][3], ad1, bb3);
            fma2(acc[2][0], ad2, bb0); fma2(acc[2][1], ad2, bb1);
            fma2(acc[2][2], ad2, bb2); fma2(acc[2][3], ad2, bb3);
            fma2(acc[3][0], ad3, bb0); fma2(acc[3][1], ad3, bb1);
            fma2(acc[3][2], ad3, bb2); fma2(acc[3][3], ad3, bb3);
        }
        __syncthreads();
    }

    int col = bn + tx * 4;
    float4 bia = *(const float4*)(bias + col);
    #pragma unroll
    for (int i2 = 0; i2 < 4; i2++) {
        float r0[4], r1[4];
        #pragma unroll
        for (int j = 0; j < 4; j++) unpack2(acc[i2][j], r0[j], r1[j]);
        float bb[4] = {bia.x, bia.y, bia.z, bia.w};
        #pragma unroll
        for (int j = 0; j < 4; j++) {
            r0[j] += bb[j]; r1[j] += bb[j];
            if (ACT == 1) { r0[j] = fmaxf(r0[j], 0.f); r1[j] = fmaxf(r1[j], 0.f); }
            if (ACT == 2) { r0[j] = tanhf(r0[j]); r1[j] = tanhf(r1[j]); }
        }
        int row = bm + ty * 8 + i2 * 2;
        *(float4*)(C + (size_t)row * ldc + col)       = make_float4(r0[0], r0[1], r0[2], r0[3]);
        *(float4*)(C + (size_t)(row + 1) * ldc + col) = make_float4(r1[0], r1[1], r1[2], r1[3]);
    }
}

// ---------------- neighborhood attention (one warp per node) ----------------
__global__ void nbr_kernel() {
    int gwarp = (blockIdx.x * blockDim.x + threadIdx.x) >> 5;
    int lane = threadIdx.x & 31;
    if (gwarp >= NN) return;
    int i = gwarp;
    int r = i >> 6, c = i & 63;

    float hi[16];
    const float* Hi = g_H2 + (size_t)i * H2DIM;
    #pragma unroll
    for (int u = 0; u < 16; u++) hi[u] = Hi[lane + 32 * u];

    int nbrs[8]; int cnt = 0;
    for (int dr = -1; dr <= 1; dr++)
        for (int dc = -1; dc <= 1; dc++) {
            if (dr == 0 && dc == 0) continue;
            int rr = r + dr, cc = c + dc;
            if (rr >= 0 && rr < 32 && cc >= 0 && cc < 64) nbrs[cnt++] = rr * 64 + cc;
        }

    float dots[8];
    for (int q = 0; q < cnt; q++) {
        const float* An = g_An + (size_t)nbrs[q] * HDIM;
        float s = 0.f;
        #pragma unroll
        for (int u = 0; u < 16; u++) s += hi[u] * An[lane + 32 * u];
        #pragma unroll
        for (int o = 16; o; o >>= 1) s += __shfl_xor_sync(0xffffffffu, s, o);
        dots[q] = s;
    }
    float m = -3.0e38f;
    for (int q = 0; q < cnt; q++) m = fmaxf(m, dots[q]);
    float ssum = 0.f;
    for (int q = 0; q < cnt; q++) { dots[q] = expf(dots[q] - m); ssum += dots[q]; }
    float inv = 1.f / ssum;

    float accv[16];
    #pragma unroll
    for (int u = 0; u < 16; u++) accv[u] = 0.f;
    for (int q = 0; q < cnt; q++) {
        float a = dots[q] * inv;
        const float* Hj = g_H2 + (size_t)nbrs[q] * H2DIM;
        #pragma unroll
        for (int u = 0; u < 16; u++) accv[u] += a * Hj[lane + 32 * u];
    }
    float* o = g_H2 + (size_t)i * H2DIM + HDIM;
    #pragma unroll
    for (int u = 0; u < 16; u++) o[lane + 32 * u] = accv[u];
}

// ---------------- template logits ----------------
__global__ void tlogits_kernel(const float* __restrict__ templates) {
    int n = blockIdx.x;
    int t = threadIdx.x >> 5, lane = threadIdx.x & 31;
    const float* p = g_P + (size_t)n * H2DIM;
    const float* tm = templates + (size_t)t * H2DIM;
    float s = 0.f;
    for (int k = lane; k < H2DIM; k += 32) s += p[k] * tm[k];
    #pragma unroll
    for (int o = 16; o; o >>= 1) s += __shfl_xor_sync(0xffffffffu, s, o);
    if (lane == 0) g_L[(size_t)n * TDIM + t] = s;
}

// ---------------- betas softmax ----------------
__global__ void betas_kernel() {
    int t = blockIdx.x, tid = threadIdx.x;
    __shared__ float red[256];
    __shared__ float smax, ssum;
    float m = -3.0e38f;
    for (int n = tid; n < NN; n += 256) m = fmaxf(m, g_L[(size_t)n * TDIM + t]);
    red[tid] = m; __syncthreads();
    for (int s = 128; s; s >>= 1) { if (tid < s) red[tid] = fmaxf(red[tid], red[tid + s]); __syncthreads(); }
    if (tid == 0) smax = red[0];
    __syncthreads();
    float acc = 0.f;
    for (int n = tid; n < NN; n += 256) acc += expf(g_L[(size_t)n * TDIM + t] - smax);
    red[tid] = acc; __syncthreads();
    for (int s = 128; s; s >>= 1) { if (tid < s) red[tid] += red[tid + s]; __syncthreads(); }
    if (tid == 0) ssum = 1.f / red[0];
    __syncthreads();
    for (int n = tid; n < NN; n += 256)
        g_betas[t * NN + n] = expf(g_L[(size_t)n * TDIM + t] - smax) * ssum;
}

// ---------------- embs partials ----------------
__global__ void embs_part_kernel() {
    __shared__ float bsh[TDIM * 512];
    int col = blockIdx.x * 128 + threadIdx.x;
    int s = blockIdx.y;
    int n0 = s * 512;
    for (int i = threadIdx.x; i < TDIM * 512; i += 128) {
        int t = i / 512, nl = i % 512;
        bsh[i] = g_betas[t * NN + n0 + nl];
    }
    __syncthreads();
    float acc[TDIM];
    #pragma unroll
    for (int t = 0; t < TDIM; t++) acc[t] = 0.f;
    for (int nl = 0; nl < 512; nl++) {
        float h = g_H2[(size_t)(n0 + nl) * H2DIM + col];
        #pragma unroll
        for (int t = 0; t < TDIM; t++) acc[t] += bsh[t * 512 + nl] * h;
    }
    #pragma unroll
    for (int t = 0; t < TDIM; t++)
        g_embs_part[(size_t)(s * TDIM + t) * H2DIM + col] = acc[t];
}

// ---------------- final ----------------
__global__ void final_kernel(const float* __restrict__ glob_w1, const float* __restrict__ glob_b1,
                             const float* __restrict__ glob_w2, const float* __restrict__ glob_b2,
                             const float* __restrict__ cls_w,  const float* __restrict__ cls_b,
                             float* __restrict__ out, int out_size) {
    __shared__ float esh[TDIM * H2DIM];
    __shared__ float vsh[1280];
    __shared__ float gam[TDIM];
    __shared__ float psh[2];
    int tid = threadIdx.x;

    for (int i = tid; i < TDIM * H2DIM; i += 256) {
        float s = 0.f;
        #pragma unroll
        for (int p = 0; p < NSPLIT; p++) s += g_embs_part[(size_t)p * TDIM * H2DIM + i];
        esh[i] = s;
    }
    __syncthreads();

    for (int idx = tid; idx < TDIM * 128; idx += 256) {
        int t = idx >> 7, j = idx & 127;
        const float* w = glob_w1 + (size_t)j * H2DIM;
        const float* e = esh + t * H2DIM;
        float s = glob_b1[j];
        for (int k = 0; k < H2DIM; k++) s += w[k] * e[k];
        vsh[idx] = tanhf(s);
    }
    __syncthreads();

    if (tid < TDIM) {
        float s = glob_b2[0];
        for (int j = 0; j < 128; j++) s += glob_w2[j] * vsh[tid * 128 + j];
        gam[tid] = s;
    }
    __syncthreads();
    if (tid == 0) {
        float m = gam[0];
        for (int t = 1; t < TDIM; t++) m = fmaxf(m, gam[t]);
        float ss = 0.f;
        for (int t = 0; t < TDIM; t++) { gam[t] = expf(gam[t] - m); ss += gam[t]; }
        float inv = 1.f / ss;
        for (int t = 0; t < TDIM; t++) gam[t] *= inv;
    }
    __syncthreads();

    float* Msh = vsh;
    for (int k = tid; k < H2DIM; k += 256) {
        float s = 0.f;
        #pragma unroll
        for (int t = 0; t < TDIM; t++) s += gam[t] * esh[t * H2DIM + k];
        Msh[k] = s;
    }
    __syncthreads();

    if (tid < 64) {
        int c = tid >> 5, lane = tid & 31;
        float s = 0.f;
        for (int k = lane; k < H2DIM; k += 32) s += cls_w[(size_t)c * H2DIM + k] * Msh[k];
        #pragma unroll
        for (int o = 16; o; o >>= 1) s += __shfl_xor_sync(0xffffffffu, s, o);
        if (lane == 0) {
            float p = 1.f / (1.f + expf(-(s + cls_b[c])));
            psh[c] = p;
            if (c < out_size) out[c] = p;
        }
    }
    __syncthreads();
    if (tid == 0 && out_size > 2) out[2] = (psh[1] > psh[0]) ? 1.0f : 0.0f;

    for (int n = tid; n < NN; n += 256) {
        float s = 0.f;
        #pragma unroll
        for (int t = 0; t < TDIM; t++) s += gam[t] * g_betas[t * NN + n];
        if (3 + n < out_size) out[3 + n] = s;
    }
}

// ---------------- launch ----------------
extern "C" void kernel_launch(void* const* d_in, const int* in_sizes, int n_in,
                              void* d_out, int out_size) {
    const float* x        = (const float*)d_in[0];
    const float* conv1_w  = (const float*)d_in[2];
    const float* conv1_b  = (const float*)d_in[3];
    const float* conv2_w  = (const float*)d_in[4];
    const float* conv2_b  = (const float*)d_in[5];
    const float* fc1_w    = (const float*)d_in[6];
    const float* fc1_b    = (const float*)d_in[7];
    const float* fc2_w    = (const float*)d_in[8];
    const float* fc2_b    = (const float*)d_in[9];
    const float* nbr_w    = (const float*)d_in[10];
    const float* nbr_b    = (const float*)d_in[11];
    const float* templates= (const float*)d_in[12];
    const float* proto_w  = (const float*)d_in[13];
    const float* proto_b  = (const float*)d_in[14];
    const float* glob_w1  = (const float*)d_in[15];
    const float* glob_b1  = (const float*)d_in[16];
    const float* glob_w2  = (const float*)d_in[17];
    const float* glob_b2  = (const float*)d_in[18];
    const float* cls_w    = (const float*)d_in[19];
    const float* cls_b    = (const float*)d_in[20];
    float* out = (float*)d_out;

    float* H0 = nullptr; float* H1 = nullptr; float* H2 = nullptr;
    float* An = nullptr; float* P  = nullptr;
    cudaGetSymbolAddress((void**)&H0, g_H0);
    cudaGetSymbolAddress((void**)&H1, g_H1);
    cudaGetSymbolAddress((void**)&H2, g_H2);
    cudaGetSymbolAddress((void**)&An, g_An);
    cudaGetSymbolAddress((void**)&P,  g_P);

    static const size_t conv_smem = S_TOTALF * sizeof(float);
    cudaFuncSetAttribute(conv_fused_kernel, cudaFuncAttributeMaxDynamicSharedMemorySize, (int)conv_smem);

    // 5 no-ops so ncu (-s 5 -c 1) captures conv_fused
    for (int i = 0; i < 5; i++) noop_kernel<<<1, 32>>>();

    conv_fused_kernel<<<NN, 512, conv_smem>>>(x, conv1_w, conv1_b, conv2_w, conv2_b);

    // fc1: relu(H0 @ fc1_w^T + b) -> H1
    sgemm128<1><<<dim3(HDIM / 64, NN / 128), 256>>>(H0, fc1_w, fc1_b, H1, H0DIM, H0DIM, H0DIM, HDIM);
    // fc2: -> H2[:, :512], relu (ldc = 1024)
    sgemm128<1><<<dim3(HDIM / 64, NN / 128), 256>>>(H1, fc2_w, fc2_b, H2, HDIM, HDIM, HDIM, H2DIM);
    // An = tanh(H @ nbr_w^T + b)  (A = H2 first 512 cols, lda = 1024)
    sgemm128<2><<<dim3(HDIM / 64, NN / 128), 256>>>(H2, nbr_w, nbr_b, An, HDIM, H2DIM, HDIM, HDIM);
    nbr_kernel<<<NN / 8, 256>>>();
    // P = tanh(H2 @ proto_w^T + b)
    sgemm128<2><<<dim3(H2DIM / 64, NN / 128), 256>>>(H2, proto_w, proto_b, P, H2DIM, H2DIM, H2DIM, H2DIM);

    tlogits_kernel<<<NN, 320>>>(templates);
    betas_kernel<<<TDIM, 256>>>();
    embs_part_kernel<<<dim3(H2DIM / 128, NSPLIT), 128>>>();
    final_kernel<<<1, 256>>>(glob_w1, glob_b1, glob_w2, glob_b2, cls_w, cls_b, out, out_size);
}

// round 5
// speedup vs baseline: 1.1834x; 1.0899x over previous
#include <cuda_runtime.h>
#include <cuda_bf16.h>
#include <math.h>

typedef unsigned long long ull;
typedef unsigned int u32;

// ---------------- problem constants ----------------
#define NN        2048
#define P1        14
#define H0DIM     1728
#define HDIM      512
#define H2DIM     1024
#define TDIM      10
#define NSPLIT    4

// conv SMEM layout (floats)
#define S_IMG     0
#define S_W1      1056
#define S_B1      1632
#define S_B2      1668
#define S_POOL1   1716
#define S_W2      8772
#define S_TOTALF  (8772 + 15552)

#define SWZ(off)  ((off) ^ (((off) >> 3) & 0x70))

// ---------------- scratch ----------------
__device__ float g_H2[(size_t)NN * H2DIM];
__device__ float g_An[(size_t)NN * HDIM];
__device__ float g_P[(size_t)NN * H2DIM];
__device__ float g_L[(size_t)NN * TDIM];
__device__ float g_betas[TDIM * NN];
__device__ float g_embs_part[NSPLIT * TDIM * H2DIM];

// bf16 split buffers (A-side rows: [hi|hi|lo], B-side weight rows: [hi|lo|hi])
__device__ __align__(256) __nv_bfloat16 g_H0s[(size_t)NN * 3 * H0DIM];
__device__ __align__(256) __nv_bfloat16 g_H1s[(size_t)NN * 3 * HDIM];
__device__ __align__(256) __nv_bfloat16 g_H2s[(size_t)NN * 3 * H2DIM];
__device__ __align__(256) __nv_bfloat16 g_fc1ws[(size_t)HDIM * 3 * H0DIM];
__device__ __align__(256) __nv_bfloat16 g_fc2ws[(size_t)HDIM * 3 * HDIM];
__device__ __align__(256) __nv_bfloat16 g_nbrws[(size_t)HDIM * 3 * HDIM];
__device__ __align__(256) __nv_bfloat16 g_protows[(size_t)H2DIM * 3 * H2DIM];

__global__ void noop_kernel() {}

__device__ __forceinline__ u32 smem_u32(const void* p) {
    u32 a; asm("{ .reg .u64 t; cvta.to.shared.u64 t, %1; cvt.u32.u64 %0, t; }" : "=r"(a) : "l"(p));
    return a;
}

// ---------------- weight split cvt: w[N,K] fp32 -> [hi|lo|hi] bf16 ----------------
__global__ void cvt_w_kernel(const float* __restrict__ w, __nv_bfloat16* __restrict__ o, int K, int total) {
    int idx = blockIdx.x * 256 + threadIdx.x;
    if (idx >= total) return;
    int n = idx / K, k = idx - n * K;
    float v = w[idx];
    __nv_bfloat16 hi = __float2bfloat16(v);
    __nv_bfloat16 lo = __float2bfloat16(v - __bfloat162float(hi));
    size_t base = (size_t)n * 3 * K + k;
    o[base] = hi; o[base + K] = lo; o[base + 2 * K] = hi;
}

// ---------------- fused conv1+pool1+conv2+pool2 ----------------
__device__ __forceinline__ ull pack2(float lo, float hi) {
    ull r; asm("mov.b64 %0, {%1, %2};" : "=l"(r) : "f"(lo), "f"(hi)); return r;
}
__device__ __forceinline__ void unpack2(ull v, float& lo, float& hi) {
    asm("mov.b64 {%0, %1}, %2;" : "=f"(lo), "=f"(hi) : "l"(v));
}
__device__ __forceinline__ void fma2(ull& d, ull a, ull b) {
    asm("fma.rn.f32x2 %0, %1, %2, %0;" : "+l"(d) : "l"(a), "l"(b));
}

__global__ __launch_bounds__(512, 2)
void conv_fused_kernel(const float* __restrict__ x,
                       const float* __restrict__ w1,
                       const float* __restrict__ b1,
                       const float* __restrict__ w2,
                       const float* __restrict__ b2) {
    extern __shared__ float sm[];
    float* s_img   = sm + S_IMG;
    float* s_w1    = sm + S_W1;
    float* s_b1    = sm + S_B1;
    float* s_b2    = sm + S_B2;
    float* s_pool1 = sm + S_POOL1;
    float* s_w2    = sm + S_W2;

    int n = blockIdx.x, tid = threadIdx.x;
    const float* xin = x + (size_t)n * 1024;

    for (int i = tid; i < 1024; i += 512) {
        int r = i >> 5, c = i & 31;
        s_img[r * 33 + c] = xin[i];
    }
    for (int i = tid; i < 576; i += 512) s_w1[i] = w1[i];
    if (tid < 36) s_b1[tid] = b1[tid];
    else if (tid >= 64 && tid < 112) s_b2[tid - 64] = b2[tid - 64];
    for (int i = tid; i < 15552; i += 512) {
        int ch = i / 324, r = i - ch * 324;
        s_w2[r * 48 + ch] = w2[i];
    }
    __syncthreads();

    if (tid < 504) {
        int ch = tid / 14, py = tid % 14;
        const float4* wp = (const float4*)&s_w1[ch * 16];
        float4 a0 = wp[0], a1 = wp[1], a2 = wp[2], a3 = wp[3];
        float wr[16] = {a0.x,a0.y,a0.z,a0.w, a1.x,a1.y,a1.z,a1.w,
                        a2.x,a2.y,a2.z,a2.w, a3.x,a3.y,a3.z,a3.w};
        float bias1 = s_b1[ch];
        float* prow = s_pool1 + ch * 196 + py * 14;
        for (int px = 0; px < 14; px++) {
            float im[5][5];
            #pragma unroll
            for (int yy = 0; yy < 5; yy++)
                #pragma unroll
                for (int xx = 0; xx < 5; xx++)
                    im[yy][xx] = s_img[(2 * py + yy) * 33 + 2 * px + xx];
            float m = -3.0e38f;
            #pragma unroll
            for (int dy = 0; dy < 2; dy++)
                #pragma unroll
                for (int dx = 0; dx < 2; dx++) {
                    float s = 0.f;
                    #pragma unroll
                    for (int ky = 0; ky < 4; ky++)
                        #pragma unroll
                        for (int kx = 0; kx < 4; kx++)
                            s += im[dy + ky][dx + kx] * wr[ky * 4 + kx];
                    m = fmaxf(m, s);
                }
            prow[px] = fmaxf(m + bias1, 0.f);
        }
    }
    __syncthreads();

    ull accp[8];
    int g = tid / 144, p = tid - g * 144;
    if (tid < 432) {
        int cy = p / 12, cx = p - cy * 12;
        #pragma unroll
        for (int j = 0; j < 8; j++) accp[j] = 0ull;
        const float* inb = s_pool1 + cy * 14 + cx;
        const float* wgb = s_w2 + g * 16;
        for (int c = 0; c < 36; c++) {
            #pragma unroll
            for (int k = 0; k < 9; k++) {
                float v = inb[c * 196 + (k / 3) * 14 + (k % 3)];
                ull vv = pack2(v, v);
                const ull* q = (const ull*)(wgb + (c * 9 + k) * 48);
                fma2(accp[0], q[0], vv); fma2(accp[1], q[1], vv);
                fma2(accp[2], q[2], vv); fma2(accp[3], q[3], vv);
                fma2(accp[4], q[4], vv); fma2(accp[5], q[5], vv);
                fma2(accp[6], q[6], vv); fma2(accp[7], q[7], vv);
            }
        }
    }
    __syncthreads();
    if (tid < 432) {
        float* o = s_w2 + p * 49 + g * 16;
        #pragma unroll
        for (int j = 0; j < 8; j++) {
            float lo, hi; unpack2(accp[j], lo, hi);
            o[2 * j] = lo; o[2 * j + 1] = hi;
        }
    }
    __syncthreads();

    __nv_bfloat16* outb = g_H0s + (size_t)n * 3 * H0DIM;
    for (int o = tid; o < 1728; o += 512) {
        int ch = o / 36, pp = o - ch * 36;
        int py = pp / 6, px = pp - py * 6;
        int i00 = (2 * py) * 12 + 2 * px;
        float m = fmaxf(fmaxf(s_w2[i00 * 49 + ch],        s_w2[(i00 + 1)  * 49 + ch]),
                        fmaxf(s_w2[(i00 + 12) * 49 + ch], s_w2[(i00 + 13) * 49 + ch]));
        float v = fmaxf(m + s_b2[ch], 0.f);
        __nv_bfloat16 hi = __float2bfloat16(v);
        __nv_bfloat16 lo = __float2bfloat16(v - __bfloat162float(hi));
        outb[o] = hi; outb[1728 + o] = hi; outb[3456 + o] = lo;
    }
}

// ---------------- mma.sync bf16 GEMM: C = act(A @ B^T + bias), 3x-bf16 fp32 emu --
// A: [M, 3K] bf16 via (rsA, ssA), B: [N, 3K] bf16 via (rsB, ssB). Tile 128x64.
// 8 warps: warp tile 64(M) x 16(N); mma m16n8k16; K-chunk 64, double buffer.
template <int ACT, bool WF, bool WS>
__global__ __launch_bounds__(256)
void mma_gemm(const __nv_bfloat16* __restrict__ A, const __nv_bfloat16* __restrict__ B,
              const float* __restrict__ bias, float* __restrict__ Cf, __nv_bfloat16* __restrict__ Cs,
              int K, int rsA, int ssA, int rsB, int ssB, int ldc, int ldcs, int slotC) {
    extern __shared__ char smem[];
    u32 sb = smem_u32(smem);
    const int tid = threadIdx.x, wid = tid >> 5, lane = tid & 31;
    const int bm = blockIdx.y * 128, bn = blockIdx.x * 64;
    const int wm = wid & 1, wn = wid >> 1;

    const int lr = tid >> 3, lg = tid & 7;   // load mapping (row, 16B-group)

    uint4 ra[4], rb[2];
    auto gload = [&](int kc) {
        int slot = kc / K, off = kc - slot * K;
        const __nv_bfloat16* Ab = A + (size_t)bm * rsA + (size_t)slot * ssA + off;
        #pragma unroll
        for (int i = 0; i < 4; i++)
            ra[i] = *(const uint4*)(Ab + (size_t)(lr + i * 32) * rsA + lg * 8);
        const __nv_bfloat16* Bb = B + (size_t)bn * rsB + (size_t)slot * ssB + off;
        #pragma unroll
        for (int i = 0; i < 2; i++)
            rb[i] = *(const uint4*)(Bb + (size_t)(lr + i * 32) * rsB + lg * 8);
    };
    auto sstore = [&](int buf) {
        char* pA = smem + buf * 24576;
        char* pB = smem + buf * 24576 + 16384;
        #pragma unroll
        for (int i = 0; i < 4; i++)
            *(uint4*)(pA + SWZ((lr + i * 32) * 128 + lg * 16)) = ra[i];
        #pragma unroll
        for (int i = 0; i < 2; i++)
            *(uint4*)(pB + SWZ((lr + i * 32) * 128 + lg * 16)) = rb[i];
    };

    float acc[4][2][4];
    #pragma unroll
    for (int mi = 0; mi < 4; mi++)
        #pragma unroll
        for (int ni = 0; ni < 2; ni++)
            #pragma unroll
            for (int j = 0; j < 4; j++) acc[mi][ni][j] = 0.f;

    const int nch = (3 * K) / 64;
    gload(0); sstore(0); __syncthreads();

    for (int c = 0; c < nch; c++) {
        int buf = c & 1;
        if (c + 1 < nch) gload((c + 1) * 64);
        u32 sA = sb + buf * 24576, sBB = sb + buf * 24576 + 16384;
        #pragma unroll
        for (int ks = 0; ks < 4; ks++) {
            u32 a[4][4], b[2][2];
            #pragma unroll
            for (int mi = 0; mi < 4; mi++) {
                int row = wm * 64 + mi * 16 + (lane & 15);
                int g = ks * 2 + (lane >> 4);
                u32 ad = sA + SWZ(row * 128 + g * 16);
                asm volatile("ldmatrix.sync.aligned.m8n8.x4.shared.b16 {%0,%1,%2,%3}, [%4];"
                             : "=r"(a[mi][0]), "=r"(a[mi][1]), "=r"(a[mi][2]), "=r"(a[mi][3]) : "r"(ad));
            }
            #pragma unroll
            for (int ni = 0; ni < 2; ni++) {
                int row = wn * 16 + ni * 8 + (lane & 7);
                int g = ks * 2 + ((lane >> 3) & 1);
                u32 ad = sBB + SWZ(row * 128 + g * 16);
                asm volatile("ldmatrix.sync.aligned.m8n8.x2.shared.b16 {%0,%1}, [%2];"
                             : "=r"(b[ni][0]), "=r"(b[ni][1]) : "r"(ad));
            }
            #pragma unroll
            for (int mi = 0; mi < 4; mi++)
                #pragma unroll
                for (int ni = 0; ni < 2; ni++)
                    asm volatile("mma.sync.aligned.m16n8k16.row.col.f32.bf16.bf16.f32 "
                                 "{%0,%1,%2,%3}, {%4,%5,%6,%7}, {%8,%9}, {%0,%1,%2,%3};"
                                 : "+f"(acc[mi][ni][0]), "+f"(acc[mi][ni][1]),
                                   "+f"(acc[mi][ni][2]), "+f"(acc[mi][ni][3])
                                 : "r"(a[mi][0]), "r"(a[mi][1]), "r"(a[mi][2]), "r"(a[mi][3]),
                                   "r"(b[ni][0]), "r"(b[ni][1]));
        }
        __syncthreads();
        if (c + 1 < nch) { sstore(buf ^ 1); __syncthreads(); }
    }

    // epilogue
    #pragma unroll
    for (int ni = 0; ni < 2; ni++) {
        int c0 = bn + wn * 16 + ni * 8 + (lane & 3) * 2;
        float b0 = bias[c0], b1 = bias[c0 + 1];
        #pragma unroll
        for (int mi = 0; mi < 4; mi++) {
            int r0 = bm + wm * 64 + mi * 16 + (lane >> 2);
            float v0 = acc[mi][ni][0] + b0, v1 = acc[mi][ni][1] + b1;
            float v2 = acc[mi][ni][2] + b0, v3 = acc[mi][ni][3] + b1;
            if (ACT == 1) { v0 = fmaxf(v0, 0.f); v1 = fmaxf(v1, 0.f); v2 = fmaxf(v2, 0.f); v3 = fmaxf(v3, 0.f); }
            if (ACT == 2) { v0 = tanhf(v0); v1 = tanhf(v1); v2 = tanhf(v2); v3 = tanhf(v3); }
            if (WF) {
                *(float2*)(Cf + (size_t)r0 * ldc + c0)       = make_float2(v0, v1);
                *(float2*)(Cf + (size_t)(r0 + 8) * ldc + c0) = make_float2(v2, v3);
            }
            if (WS) {
                __nv_bfloat16* s0 = Cs + (size_t)r0 * ldcs + c0;
                __nv_bfloat16* s1 = Cs + (size_t)(r0 + 8) * ldcs + c0;
                float vv[2][2] = {{v0, v1}, {v2, v3}};
                __nv_bfloat16* sp[2] = {s0, s1};
                #pragma unroll
                for (int rr = 0; rr < 2; rr++)
                    #pragma unroll
                    for (int jj = 0; jj < 2; jj++) {
                        float v = vv[rr][jj];
                        __nv_bfloat16 hi = __float2bfloat16(v);
                        __nv_bfloat16 lo = __float2bfloat16(v - __bfloat162float(hi));
                        sp[rr][jj] = hi; sp[rr][slotC + jj] = hi; sp[rr][2 * slotC + jj] = lo;
                    }
            }
        }
    }
}

// ---------------- neighborhood attention (one warp per node) ----------------
__global__ void nbr_kernel() {
    int gwarp = (blockIdx.x * blockDim.x + threadIdx.x) >> 5;
    int lane = threadIdx.x & 31;
    if (gwarp >= NN) return;
    int i = gwarp;
    int r = i >> 6, c = i & 63;

    float hi[16];
    const float* Hi = g_H2 + (size_t)i * H2DIM;
    #pragma unroll
    for (int u = 0; u < 16; u++) hi[u] = Hi[lane + 32 * u];

    int nbrs[8]; int cnt = 0;
    for (int dr = -1; dr <= 1; dr++)
        for (int dc = -1; dc <= 1; dc++) {
            if (dr == 0 && dc == 0) continue;
            int rr = r + dr, cc = c + dc;
            if (rr >= 0 && rr < 32 && cc >= 0 && cc < 64) nbrs[cnt++] = rr * 64 + cc;
        }

    float dots[8];
    for (int q = 0; q < cnt; q++) {
        const float* An = g_An + (size_t)nbrs[q] * HDIM;
        float s = 0.f;
        #pragma unroll
        for (int u = 0; u < 16; u++) s += hi[u] * An[lane + 32 * u];
        #pragma unroll
        for (int o = 16; o; o >>= 1) s += __shfl_xor_sync(0xffffffffu, s, o);
        dots[q] = s;
    }
    float m = -3.0e38f;
    for (int q = 0; q < cnt; q++) m = fmaxf(m, dots[q]);
    float ssum = 0.f;
    for (int q = 0; q < cnt; q++) { dots[q] = expf(dots[q] - m); ssum += dots[q]; }
    float inv = 1.f / ssum;

    float accv[16];
    #pragma unroll
    for (int u = 0; u < 16; u++) accv[u] = 0.f;
    for (int q = 0; q < cnt; q++) {
        float a = dots[q] * inv;
        const float* Hj = g_H2 + (size_t)nbrs[q] * H2DIM;
        #pragma unroll
        for (int u = 0; u < 16; u++) accv[u] += a * Hj[lane + 32 * u];
    }
    float* o = g_H2 + (size_t)i * H2DIM + HDIM;
    __nv_bfloat16* os = g_H2s + (size_t)i * 3 * H2DIM;
    #pragma unroll
    for (int u = 0; u < 16; u++) {
        float v = accv[u];
        int col = 512 + lane + 32 * u;
        o[lane + 32 * u] = v;
        __nv_bfloat16 vh = __float2bfloat16(v);
        __nv_bfloat16 vl = __float2bfloat16(v - __bfloat162float(vh));
        os[col] = vh; os[1024 + col] = vh; os[2048 + col] = vl;
    }
}

// ---------------- template logits ----------------
__global__ void tlogits_kernel(const float* __restrict__ templates) {
    int n = blockIdx.x;
    int t = threadIdx.x >> 5, lane = threadIdx.x & 31;
    const float* p = g_P + (size_t)n * H2DIM;
    const float* tm = templates + (size_t)t * H2DIM;
    float s = 0.f;
    for (int k = lane; k < H2DIM; k += 32) s += p[k] * tm[k];
    #pragma unroll
    for (int o = 16; o; o >>= 1) s += __shfl_xor_sync(0xffffffffu, s, o);
    if (lane == 0) g_L[(size_t)n * TDIM + t] = s;
}

// ---------------- betas softmax ----------------
__global__ void betas_kernel() {
    int t = blockIdx.x, tid = threadIdx.x;
    __shared__ float red[256];
    __shared__ float smax, ssum;
    float m = -3.0e38f;
    for (int n = tid; n < NN; n += 256) m = fmaxf(m, g_L[(size_t)n * TDIM + t]);
    red[tid] = m; __syncthreads();
    for (int s = 128; s; s >>= 1) { if (tid < s) red[tid] = fmaxf(red[tid], red[tid + s]); __syncthreads(); }
    if (tid == 0) smax = red[0];
    __syncthreads();
    float acc = 0.f;
    for (int n = tid; n < NN; n += 256) acc += expf(g_L[(size_t)n * TDIM + t] - smax);
    red[tid] = acc; __syncthreads();
    for (int s = 128; s; s >>= 1) { if (tid < s) red[tid] += red[tid + s]; __syncthreads(); }
    if (tid == 0) ssum = 1.f / red[0];
    __syncthreads();
    for (int n = tid; n < NN; n += 256)
        g_betas[t * NN + n] = expf(g_L[(size_t)n * TDIM + t] - smax) * ssum;
}

// ---------------- embs partials ----------------
__global__ void embs_part_kernel() {
    __shared__ float bsh[TDIM * 512];
    int col = blockIdx.x * 128 + threadIdx.x;
    int s = blockIdx.y;
    int n0 = s * 512;
    for (int i = threadIdx.x; i < TDIM * 512; i += 128) {
        int t = i / 512, nl = i % 512;
        bsh[i] = g_betas[t * NN + n0 + nl];
    }
    __syncthreads();
    float acc[TDIM];
    #pragma unroll
    for (int t = 0; t < TDIM; t++) acc[t] = 0.f;
    for (int nl = 0; nl < 512; nl++) {
        float h = g_H2[(size_t)(n0 + nl) * H2DIM + col];
        #pragma unroll
        for (int t = 0; t < TDIM; t++) acc[t] += bsh[t * 512 + nl] * h;
    }
    #pragma unroll
    for (int t = 0; t < TDIM; t++)
        g_embs_part[(size_t)(s * TDIM + t) * H2DIM + col] = acc[t];
}

// ---------------- final ----------------
__global__ void final_kernel(const float* __restrict__ glob_w1, const float* __restrict__ glob_b1,
                             const float* __restrict__ glob_w2, const float* __restrict__ glob_b2,
                             const float* __restrict__ cls_w,  const float* __restrict__ cls_b,
                             float* __restrict__ out, int out_size) {
    __shared__ float esh[TDIM * H2DIM];
    __shared__ float vsh[1280];
    __shared__ float gam[TDIM];
    __shared__ float psh[2];
    int tid = threadIdx.x;

    for (int i = tid; i < TDIM * H2DIM; i += 256) {
        float s = 0.f;
        #pragma unroll
        for (int p = 0; p < NSPLIT; p++) s += g_embs_part[(size_t)p * TDIM * H2DIM + i];
        esh[i] = s;
    }
    __syncthreads();

    for (int idx = tid; idx < TDIM * 128; idx += 256) {
        int t = idx >> 7, j = idx & 127;
        const float* w = glob_w1 + (size_t)j * H2DIM;
        const float* e = esh + t * H2DIM;
        float s = glob_b1[j];
        for (int k = 0; k < H2DIM; k++) s += w[k] * e[k];
        vsh[idx] = tanhf(s);
    }
    __syncthreads();

    if (tid < TDIM) {
        float s = glob_b2[0];
        for (int j = 0; j < 128; j++) s += glob_w2[j] * vsh[tid * 128 + j];
        gam[tid] = s;
    }
    __syncthreads();
    if (tid == 0) {
        float m = gam[0];
        for (int t = 1; t < TDIM; t++) m = fmaxf(m, gam[t]);
        float ss = 0.f;
        for (int t = 0; t < TDIM; t++) { gam[t] = expf(gam[t] - m); ss += gam[t]; }
        float inv = 1.f / ss;
        for (int t = 0; t < TDIM; t++) gam[t] *= inv;
    }
    __syncthreads();

    float* Msh = vsh;
    for (int k = tid; k < H2DIM; k += 256) {
        float s = 0.f;
        #pragma unroll
        for (int t = 0; t < TDIM; t++) s += gam[t] * esh[t * H2DIM + k];
        Msh[k] = s;
    }
    __syncthreads();

    if (tid < 64) {
        int c = tid >> 5, lane = tid & 31;
        float s = 0.f;
        for (int k = lane; k < H2DIM; k += 32) s += cls_w[(size_t)c * H2DIM + k] * Msh[k];
        #pragma unroll
        for (int o = 16; o; o >>= 1) s += __shfl_xor_sync(0xffffffffu, s, o);
        if (lane == 0) {
            float p = 1.f / (1.f + expf(-(s + cls_b[c])));
            psh[c] = p;
            if (c < out_size) out[c] = p;
        }
    }
    __syncthreads();
    if (tid == 0 && out_size > 2) out[2] = (psh[1] > psh[0]) ? 1.0f : 0.0f;

    for (int n = tid; n < NN; n += 256) {
        float s = 0.f;
        #pragma unroll
        for (int t = 0; t < TDIM; t++) s += gam[t] * g_betas[t * NN + n];
        if (3 + n < out_size) out[3 + n] = s;
    }
}

// ---------------- launch ----------------
extern "C" void kernel_launch(void* const* d_in, const int* in_sizes, int n_in,
                              void* d_out, int out_size) {
    const float* x        = (const float*)d_in[0];
    const float* conv1_w  = (const float*)d_in[2];
    const float* conv1_b  = (const float*)d_in[3];
    const float* conv2_w  = (const float*)d_in[4];
    const float* conv2_b  = (const float*)d_in[5];
    const float* fc1_w    = (const float*)d_in[6];
    const float* fc1_b    = (const float*)d_in[7];
    const float* fc2_w    = (const float*)d_in[8];
    const float* fc2_b    = (const float*)d_in[9];
    const float* nbr_w    = (const float*)d_in[10];
    const float* nbr_b    = (const float*)d_in[11];
    const float* templates= (const float*)d_in[12];
    const float* proto_w  = (const float*)d_in[13];
    const float* proto_b  = (const float*)d_in[14];
    const float* glob_w1  = (const float*)d_in[15];
    const float* glob_b1  = (const float*)d_in[16];
    const float* glob_w2  = (const float*)d_in[17];
    const float* glob_b2  = (const float*)d_in[18];
    const float* cls_w    = (const float*)d_in[19];
    const float* cls_b    = (const float*)d_in[20];
    float* out = (float*)d_out;

    float *H2, *An, *P;
    __nv_bfloat16 *H0s, *H1s, *H2s, *fc1ws, *fc2ws, *nbrws, *protows;
    cudaGetSymbolAddress((void**)&H2, g_H2);
    cudaGetSymbolAddress((void**)&An, g_An);
    cudaGetSymbolAddress((void**)&P,  g_P);
    cudaGetSymbolAddress((void**)&H0s, g_H0s);
    cudaGetSymbolAddress((void**)&H1s, g_H1s);
    cudaGetSymbolAddress((void**)&H2s, g_H2s);
    cudaGetSymbolAddress((void**)&fc1ws, g_fc1ws);
    cudaGetSymbolAddress((void**)&fc2ws, g_fc2ws);
    cudaGetSymbolAddress((void**)&nbrws, g_nbrws);
    cudaGetSymbolAddress((void**)&protows, g_protows);

    const size_t conv_smem = S_TOTALF * sizeof(float);
    cudaFuncSetAttribute(conv_fused_kernel, cudaFuncAttributeMaxDynamicSharedMemorySize, (int)conv_smem);
    const int gsmem = 49152;
    cudaFuncSetAttribute(mma_gemm<1, false, true>,  cudaFuncAttributeMaxDynamicSharedMemorySize, gsmem);
    cudaFuncSetAttribute(mma_gemm<1, true,  true>,  cudaFuncAttributeMaxDynamicSharedMemorySize, gsmem);
    cudaFuncSetAttribute(mma_gemm<2, true,  false>, cudaFuncAttributeMaxDynamicSharedMemorySize, gsmem);

    // 4 noops -> ncu (-s 5 -c 1, +1 harness-side launch) captures conv_fused
    for (int i = 0; i < 4; i++) noop_kernel<<<1, 32>>>();

    conv_fused_kernel<<<NN, 512, conv_smem>>>(x, conv1_w, conv1_b, conv2_w, conv2_b);

    // weight splits
    cvt_w_kernel<<<(HDIM * H0DIM + 255) / 256, 256>>>(fc1_w, fc1ws, H0DIM, HDIM * H0DIM);
    cvt_w_kernel<<<(HDIM * HDIM + 255) / 256, 256>>>(fc2_w, fc2ws, HDIM, HDIM * HDIM);
    cvt_w_kernel<<<(HDIM * HDIM + 255) / 256, 256>>>(nbr_w, nbrws, HDIM, HDIM * HDIM);
    cvt_w_kernel<<<(H2DIM * H2DIM + 255) / 256, 256>>>(proto_w, protows, H2DIM, H2DIM * H2DIM);

    // fc1: relu -> H1s split only
    mma_gemm<1, false, true><<<dim3(HDIM / 64, NN / 128), 256, gsmem>>>(
        H0s, fc1ws, fc1_b, nullptr, H1s, H0DIM, 3 * H0DIM, H0DIM, 3 * H0DIM, H0DIM, 0, 3 * HDIM, HDIM);
    // fc2: relu -> H2[:, :512] fp32 + H2s split
    mma_gemm<1, true, true><<<dim3(HDIM / 64, NN / 128), 256, gsmem>>>(
        H1s, fc2ws, fc2_b, H2, H2s, HDIM, 3 * HDIM, HDIM, 3 * HDIM, HDIM, H2DIM, 3 * H2DIM, H2DIM);
    // An = tanh(H @ nbr_w^T + b)
    mma_gemm<2, true, false><<<dim3(HDIM / 64, NN / 128), 256, gsmem>>>(
        H2s, nbrws, nbr_b, An, nullptr, HDIM, 3 * H2DIM, H2DIM, 3 * HDIM, HDIM, HDIM, 0, 0);
    nbr_kernel<<<NN / 8, 256>>>();
    // P = tanh(H2 @ proto_w^T + b)
    mma_gemm<2, true, false><<<dim3(H2DIM / 64, NN / 128), 256, gsmem>>>(
        H2s, protows, proto_b, P, nullptr, H2DIM, 3 * H2DIM, H2DIM, 3 * H2DIM, H2DIM, H2DIM, 0, 0);

    tlogits_kernel<<<NN, 320>>>(templates);
    betas_kernel<<<TDIM, 256>>>();
    embs_part_kernel<<<dim3(H2DIM / 128, NSPLIT), 128>>>();
    final_kernel<<<1, 256>>>(glob_w1, glob_b1, glob_w2, glob_b2, cls_w, cls_b, out, out_size);
}

// round 6
// speedup vs baseline: 1.1921x; 1.0073x over previous
#include <cuda_runtime.h>
#include <cuda_bf16.h>
#include <math.h>

typedef unsigned long long ull;
typedef unsigned int u32;

// ---------------- problem constants ----------------
#define NN        2048
#define P1        14
#define H0DIM     1728
#define HDIM      512
#define H2DIM     1024
#define TDIM      10
#define NSPLIT    4

// conv SMEM layout (floats)
#define S_IMG     0                       // 32x33 = 1056
#define S_W1      1056                    // 576
#define S_B1      1632                    // 36
#define S_B2      1668                    // 48
#define S_POOL1   1716                    // 7056
#define S_W2      8772                    // 324 rows * stride 50 = 16200 (reused as out, stride 49)
#define S_TOTALF  (8772 + 16200)          // 24972 floats = 99888 B

#define W2STRIDE  50

#define SWZ(off)  ((off) ^ (((off) >> 3) & 0x70))

// ---------------- scratch ----------------
__device__ float g_H2[(size_t)NN * H2DIM];
__device__ float g_An[(size_t)NN * HDIM];
__device__ float g_P[(size_t)NN * H2DIM];
__device__ float g_L[(size_t)NN * TDIM];
__device__ float g_betas[TDIM * NN];
__device__ float g_embs_part[NSPLIT * TDIM * H2DIM];

// bf16 split buffers (A-side rows: [hi|hi|lo], B-side weight rows: [hi|lo|hi])
__device__ __align__(256) __nv_bfloat16 g_H0s[(size_t)NN * 3 * H0DIM];
__device__ __align__(256) __nv_bfloat16 g_H1s[(size_t)NN * 3 * HDIM];
__device__ __align__(256) __nv_bfloat16 g_H2s[(size_t)NN * 3 * H2DIM];
__device__ __align__(256) __nv_bfloat16 g_fc1ws[(size_t)HDIM * 3 * H0DIM];
__device__ __align__(256) __nv_bfloat16 g_fc2ws[(size_t)HDIM * 3 * HDIM];
__device__ __align__(256) __nv_bfloat16 g_nbrws[(size_t)HDIM * 3 * HDIM];
__device__ __align__(256) __nv_bfloat16 g_protows[(size_t)H2DIM * 3 * H2DIM];

__global__ void noop_kernel() {}

__device__ __forceinline__ u32 smem_u32(const void* p) {
    u32 a; asm("{ .reg .u64 t; cvta.to.shared.u64 t, %1; cvt.u32.u64 %0, t; }" : "=r"(a) : "l"(p));
    return a;
}

// ---------------- weight split cvt: w[N,K] fp32 -> [hi|lo|hi] bf16 ----------------
__global__ void cvt_w_kernel(const float* __restrict__ w, __nv_bfloat16* __restrict__ o, int K, int total) {
    int idx = blockIdx.x * 256 + threadIdx.x;
    if (idx >= total) return;
    int n = idx / K, k = idx - n * K;
    float v = w[idx];
    __nv_bfloat16 hi = __float2bfloat16(v);
    __nv_bfloat16 lo = __float2bfloat16(v - __bfloat162float(hi));
    size_t base = (size_t)n * 3 * K + k;
    o[base] = hi; o[base + K] = lo; o[base + 2 * K] = hi;
}

// ---------------- fused conv1+pool1+conv2+pool2 ----------------
__device__ __forceinline__ ull pack2(float lo, float hi) {
    ull r; asm("mov.b64 %0, {%1, %2};" : "=l"(r) : "f"(lo), "f"(hi)); return r;
}
__device__ __forceinline__ void unpack2(ull v, float& lo, float& hi) {
    asm("mov.b64 {%0, %1}, %2;" : "=f"(lo), "=f"(hi) : "l"(v));
}
__device__ __forceinline__ void fma2(ull& d, ull a, ull b) {
    asm("fma.rn.f32x2 %0, %1, %2, %0;" : "+l"(d) : "l"(a), "l"(b));
}

__global__ __launch_bounds__(512, 2)
void conv_fused_kernel(const float* __restrict__ x,
                       const float* __restrict__ w1,
                       const float* __restrict__ b1,
                       const float* __restrict__ w2,
                       const float* __restrict__ b2) {
    extern __shared__ float sm[];
    float* s_img   = sm + S_IMG;
    float* s_w1    = sm + S_W1;
    float* s_b1    = sm + S_B1;
    float* s_b2    = sm + S_B2;
    float* s_pool1 = sm + S_POOL1;
    float* s_w2    = sm + S_W2;

    int n = blockIdx.x, tid = threadIdx.x;
    const float* xin = x + (size_t)n * 1024;

    for (int i = tid; i < 1024; i += 512) {
        int r = i >> 5, c = i & 31;
        s_img[r * 33 + c] = xin[i];
    }
    for (int i = tid; i < 576; i += 512) s_w1[i] = w1[i];
    if (tid < 36) s_b1[tid] = b1[tid];
    else if (tid >= 64 && tid < 112) s_b2[tid - 64] = b2[tid - 64];
    // conv2 weights: w2 linear = ch*324 + r -> s_w2[r*50 + ch] (stride 50: 2-way max conflict, ull-aligned)
    for (int i = tid; i < 15552; i += 512) {
        int ch = i / 324, r = i - ch * 324;
        s_w2[r * W2STRIDE + ch] = w2[i];
    }
    __syncthreads();

    // --- conv1 + relu + pool: row-accumulation (low register pressure) ---
    if (tid < 504) {
        int ch = tid / 14, py = tid % 14;
        const float4* wp = (const float4*)&s_w1[ch * 16];
        float4 a0 = wp[0], a1 = wp[1], a2 = wp[2], a3 = wp[3];
        float wr[16] = {a0.x,a0.y,a0.z,a0.w, a1.x,a1.y,a1.z,a1.w,
                        a2.x,a2.y,a2.z,a2.w, a3.x,a3.y,a3.z,a3.w};
        float bias1 = s_b1[ch];
        float* prow = s_pool1 + ch * 196 + py * 14;
        const float* ibase = s_img + (2 * py) * 33;
        for (int px = 0; px < 14; px++) {
            float s00 = 0.f, s01 = 0.f, s10 = 0.f, s11 = 0.f;
            const float* ip = ibase + 2 * px;
            #pragma unroll
            for (int yy = 0; yy < 5; yy++) {
                float r0 = ip[yy * 33 + 0], r1 = ip[yy * 33 + 1], r2 = ip[yy * 33 + 2];
                float r3 = ip[yy * 33 + 3], r4 = ip[yy * 33 + 4];
                if (yy <= 3) {
                    const float* w = wr + yy * 4;
                    s00 += r0 * w[0] + r1 * w[1] + r2 * w[2] + r3 * w[3];
                    s01 += r1 * w[0] + r2 * w[1] + r3 * w[2] + r4 * w[3];
                }
                if (yy >= 1) {
                    const float* w = wr + (yy - 1) * 4;
                    s10 += r0 * w[0] + r1 * w[1] + r2 * w[2] + r3 * w[3];
                    s11 += r1 * w[0] + r2 * w[1] + r3 * w[2] + r4 * w[3];
                }
            }
            float m = fmaxf(fmaxf(s00, s01), fmaxf(s10, s11));
            prow[px] = fmaxf(m + bias1, 0.f);
        }
    }
    __syncthreads();

    // --- conv2: thread = (16-ch group g, position p); packed f32x2 acc ---
    ull accp[8];
    int g = tid / 144, p = tid - g * 144;
    if (tid < 432) {
        int cy = p / 12, cx = p - cy * 12;
        #pragma unroll
        for (int j = 0; j < 8; j++) accp[j] = 0ull;
        const float* inb = s_pool1 + cy * 14 + cx;
        const float* wgb = s_w2 + g * 16;
        for (int c = 0; c < 36; c++) {
            #pragma unroll
            for (int k = 0; k < 9; k++) {
                float v = inb[c * 196 + (k / 3) * 14 + (k % 3)];
                ull vv = pack2(v, v);
                const ull* q = (const ull*)(wgb + (c * 9 + k) * W2STRIDE);
                fma2(accp[0], q[0], vv); fma2(accp[1], q[1], vv);
                fma2(accp[2], q[2], vv); fma2(accp[3], q[3], vv);
                fma2(accp[4], q[4], vv); fma2(accp[5], q[5], vv);
                fma2(accp[6], q[6], vv); fma2(accp[7], q[7], vv);
            }
        }
    }
    __syncthreads();   // weights done -> reuse s_w2 region as out buffer (stride 49)
    if (tid < 432) {
        float* o = s_w2 + p * 49 + g * 16;
        #pragma unroll
        for (int j = 0; j < 8; j++) {
            float lo, hi; unpack2(accp[j], lo, hi);
            o[2 * j] = lo; o[2 * j + 1] = hi;
        }
    }
    __syncthreads();

    __nv_bfloat16* outb = g_H0s + (size_t)n * 3 * H0DIM;
    for (int o = tid; o < 1728; o += 512) {
        int ch = o / 36, pp = o - ch * 36;
        int py = pp / 6, px = pp - py * 6;
        int i00 = (2 * py) * 12 + 2 * px;
        float m = fmaxf(fmaxf(s_w2[i00 * 49 + ch],        s_w2[(i00 + 1)  * 49 + ch]),
                        fmaxf(s_w2[(i00 + 12) * 49 + ch], s_w2[(i00 + 13) * 49 + ch]));
        float v = fmaxf(m + s_b2[ch], 0.f);
        __nv_bfloat16 hi = __float2bfloat16(v);
        __nv_bfloat16 lo = __float2bfloat16(v - __bfloat162float(hi));
        outb[o] = hi; outb[1728 + o] = hi; outb[3456 + o] = lo;
    }
}

// ---------------- mma.sync bf16 GEMM: C = act(A @ B^T + bias), 3x-bf16 fp32 emu --
template <int ACT, bool WF, bool WS>
__global__ __launch_bounds__(256)
void mma_gemm(const __nv_bfloat16* __restrict__ A, const __nv_bfloat16* __restrict__ B,
              const float* __restrict__ bias, float* __restrict__ Cf, __nv_bfloat16* __restrict__ Cs,
              int K, int rsA, int ssA, int rsB, int ssB, int ldc, int ldcs, int slotC) {
    extern __shared__ char smem[];
    u32 sb = smem_u32(smem);
    const int tid = threadIdx.x, wid = tid >> 5, lane = tid & 31;
    const int bm = blockIdx.y * 128, bn = blockIdx.x * 64;
    const int wm = wid & 1, wn = wid >> 1;

    const int lr = tid >> 3, lg = tid & 7;

    uint4 ra[4], rb[2];
    auto gload = [&](int kc) {
        int slot = kc / K, off = kc - slot * K;
        const __nv_bfloat16* Ab = A + (size_t)bm * rsA + (size_t)slot * ssA + off;
        #pragma unroll
        for (int i = 0; i < 4; i++)
            ra[i] = *(const uint4*)(Ab + (size_t)(lr + i * 32) * rsA + lg * 8);
        const __nv_bfloat16* Bb = B + (size_t)bn * rsB + (size_t)slot * ssB + off;
        #pragma unroll
        for (int i = 0; i < 2; i++)
            rb[i] = *(const uint4*)(Bb + (size_t)(lr + i * 32) * rsB + lg * 8);
    };
    auto sstore = [&](int buf) {
        char* pA = smem + buf * 24576;
        char* pB = smem + buf * 24576 + 16384;
        #pragma unroll
        for (int i = 0; i < 4; i++)
            *(uint4*)(pA + SWZ((lr + i * 32) * 128 + lg * 16)) = ra[i];
        #pragma unroll
        for (int i = 0; i < 2; i++)
            *(uint4*)(pB + SWZ((lr + i * 32) * 128 + lg * 16)) = rb[i];
    };

    float acc[4][2][4];
    #pragma unroll
    for (int mi = 0; mi < 4; mi++)
        #pragma unroll
        for (int ni = 0; ni < 2; ni++)
            #pragma unroll
            for (int j = 0; j < 4; j++) acc[mi][ni][j] = 0.f;

    const int nch = (3 * K) / 64;
    gload(0); sstore(0); __syncthreads();

    for (int c = 0; c < nch; c++) {
        int buf = c & 1;
        if (c + 1 < nch) gload((c + 1) * 64);
        u32 sA = sb + buf * 24576, sBB = sb + buf * 24576 + 16384;
        #pragma unroll
        for (int ks = 0; ks < 4; ks++) {
            u32 a[4][4], b[2][2];
            #pragma unroll
            for (int mi = 0; mi < 4; mi++) {
                int row = wm * 64 + mi * 16 + (lane & 15);
                int gq = ks * 2 + (lane >> 4);
                u32 ad = sA + SWZ(row * 128 + gq * 16);
                asm volatile("ldmatrix.sync.aligned.m8n8.x4.shared.b16 {%0,%1,%2,%3}, [%4];"
                             : "=r"(a[mi][0]), "=r"(a[mi][1]), "=r"(a[mi][2]), "=r"(a[mi][3]) : "r"(ad));
            }
            #pragma unroll
            for (int ni = 0; ni < 2; ni++) {
                int row = wn * 16 + ni * 8 + (lane & 7);
                int gq = ks * 2 + ((lane >> 3) & 1);
                u32 ad = sBB + SWZ(row * 128 + gq * 16);
                asm volatile("ldmatrix.sync.aligned.m8n8.x2.shared.b16 {%0,%1}, [%2];"
                             : "=r"(b[ni][0]), "=r"(b[ni][1]) : "r"(ad));
            }
            #pragma unroll
            for (int mi = 0; mi < 4; mi++)
                #pragma unroll
                for (int ni = 0; ni < 2; ni++)
                    asm volatile("mma.sync.aligned.m16n8k16.row.col.f32.bf16.bf16.f32 "
                                 "{%0,%1,%2,%3}, {%4,%5,%6,%7}, {%8,%9}, {%0,%1,%2,%3};"
                                 : "+f"(acc[mi][ni][0]), "+f"(acc[mi][ni][1]),
                                   "+f"(acc[mi][ni][2]), "+f"(acc[mi][ni][3])
                                 : "r"(a[mi][0]), "r"(a[mi][1]), "r"(a[mi][2]), "r"(a[mi][3]),
                                   "r"(b[ni][0]), "r"(b[ni][1]));
        }
        __syncthreads();
        if (c + 1 < nch) { sstore(buf ^ 1); __syncthreads(); }
    }

    #pragma unroll
    for (int ni = 0; ni < 2; ni++) {
        int c0 = bn + wn * 16 + ni * 8 + (lane & 3) * 2;
        float b0 = bias[c0], b1 = bias[c0 + 1];
        #pragma unroll
        for (int mi = 0; mi < 4; mi++) {
            int r0 = bm + wm * 64 + mi * 16 + (lane >> 2);
            float v0 = acc[mi][ni][0] + b0, v1 = acc[mi][ni][1] + b1;
            float v2 = acc[mi][ni][2] + b0, v3 = acc[mi][ni][3] + b1;
            if (ACT == 1) { v0 = fmaxf(v0, 0.f); v1 = fmaxf(v1, 0.f); v2 = fmaxf(v2, 0.f); v3 = fmaxf(v3, 0.f); }
            if (ACT == 2) { v0 = tanhf(v0); v1 = tanhf(v1); v2 = tanhf(v2); v3 = tanhf(v3); }
            if (WF) {
                *(float2*)(Cf + (size_t)r0 * ldc + c0)       = make_float2(v0, v1);
                *(float2*)(Cf + (size_t)(r0 + 8) * ldc + c0) = make_float2(v2, v3);
            }
            if (WS) {
                __nv_bfloat16* s0 = Cs + (size_t)r0 * ldcs + c0;
                __nv_bfloat16* s1 = Cs + (size_t)(r0 + 8) * ldcs + c0;
                float vv[2][2] = {{v0, v1}, {v2, v3}};
                __nv_bfloat16* sp[2] = {s0, s1};
                #pragma unroll
                for (int rr = 0; rr < 2; rr++)
                    #pragma unroll
                    for (int jj = 0; jj < 2; jj++) {
                        float v = vv[rr][jj];
                        __nv_bfloat16 hi = __float2bfloat16(v);
                        __nv_bfloat16 lo = __float2bfloat16(v - __bfloat162float(hi));
                        sp[rr][jj] = hi; sp[rr][slotC + jj] = hi; sp[rr][2 * slotC + jj] = lo;
                    }
            }
        }
    }
}

// ---------------- neighborhood attention (one warp per node) ----------------
__global__ void nbr_kernel() {
    int gwarp = (blockIdx.x * blockDim.x + threadIdx.x) >> 5;
    int lane = threadIdx.x & 31;
    if (gwarp >= NN) return;
    int i = gwarp;
    int r = i >> 6, c = i & 63;

    float hi[16];
    const float* Hi = g_H2 + (size_t)i * H2DIM;
    #pragma unroll
    for (int u = 0; u < 16; u++) hi[u] = Hi[lane + 32 * u];

    int nbrs[8]; int cnt = 0;
    for (int dr = -1; dr <= 1; dr++)
        for (int dc = -1; dc <= 1; dc++) {
            if (dr == 0 && dc == 0) continue;
            int rr = r + dr, cc = c + dc;
            if (rr >= 0 && rr < 32 && cc >= 0 && cc < 64) nbrs[cnt++] = rr * 64 + cc;
        }

    float dots[8];
    for (int q = 0; q < cnt; q++) {
        const float* An = g_An + (size_t)nbrs[q] * HDIM;
        float s = 0.f;
        #pragma unroll
        for (int u = 0; u < 16; u++) s += hi[u] * An[lane + 32 * u];
        #pragma unroll
        for (int o = 16; o; o >>= 1) s += __shfl_xor_sync(0xffffffffu, s, o);
        dots[q] = s;
    }
    float m = -3.0e38f;
    for (int q = 0; q < cnt; q++) m = fmaxf(m, dots[q]);
    float ssum = 0.f;
    for (int q = 0; q < cnt; q++) { dots[q] = expf(dots[q] - m); ssum += dots[q]; }
    float inv = 1.f / ssum;

    float accv[16];
    #pragma unroll
    for (int u = 0; u < 16; u++) accv[u] = 0.f;
    for (int q = 0; q < cnt; q++) {
        float a = dots[q] * inv;
        const float* Hj = g_H2 + (size_t)nbrs[q] * H2DIM;
        #pragma unroll
        for (int u = 0; u < 16; u++) accv[u] += a * Hj[lane + 32 * u];
    }
    float* o = g_H2 + (size_t)i * H2DIM + HDIM;
    __nv_bfloat16* os = g_H2s + (size_t)i * 3 * H2DIM;
    #pragma unroll
    for (int u = 0; u < 16; u++) {
        float v = accv[u];
        int col = 512 + lane + 32 * u;
        o[lane + 32 * u] = v;
        __nv_bfloat16 vh = __float2bfloat16(v);
        __nv_bfloat16 vl = __float2bfloat16(v - __bfloat162float(vh));
        os[col] = vh; os[1024 + col] = vh; os[2048 + col] = vl;
    }
}

// ---------------- template logits ----------------
__global__ void tlogits_kernel(const float* __restrict__ templates) {
    int n = blockIdx.x;
    int t = threadIdx.x >> 5, lane = threadIdx.x & 31;
    const float* p = g_P + (size_t)n * H2DIM;
    const float* tm = templates + (size_t)t * H2DIM;
    float s = 0.f;
    for (int k = lane; k < H2DIM; k += 32) s += p[k] * tm[k];
    #pragma unroll
    for (int o = 16; o; o >>= 1) s += __shfl_xor_sync(0xffffffffu, s, o);
    if (lane == 0) g_L[(size_t)n * TDIM + t] = s;
}

// ---------------- betas softmax ----------------
__global__ void betas_kernel() {
    int t = blockIdx.x, tid = threadIdx.x;
    __shared__ float red[256];
    __shared__ float smax, ssum;
    float m = -3.0e38f;
    for (int n = tid; n < NN; n += 256) m = fmaxf(m, g_L[(size_t)n * TDIM + t]);
    red[tid] = m; __syncthreads();
    for (int s = 128; s; s >>= 1) { if (tid < s) red[tid] = fmaxf(red[tid], red[tid + s]); __syncthreads(); }
    if (tid == 0) smax = red[0];
    __syncthreads();
    float acc = 0.f;
    for (int n = tid; n < NN; n += 256) acc += expf(g_L[(size_t)n * TDIM + t] - smax);
    red[tid] = acc; __syncthreads();
    for (int s = 128; s; s >>= 1) { if (tid < s) red[tid] += red[tid + s]; __syncthreads(); }
    if (tid == 0) ssum = 1.f / red[0];
    __syncthreads();
    for (int n = tid; n < NN; n += 256)
        g_betas[t * NN + n] = expf(g_L[(size_t)n * TDIM + t] - smax) * ssum;
}

// ---------------- embs partials ----------------
__global__ void embs_part_kernel() {
    __shared__ float bsh[TDIM * 512];
    int col = blockIdx.x * 128 + threadIdx.x;
    int s = blockIdx.y;
    int n0 = s * 512;
    for (int i = threadIdx.x; i < TDIM * 512; i += 128) {
        int t = i / 512, nl = i % 512;
        bsh[i] = g_betas[t * NN + n0 + nl];
    }
    __syncthreads();
    float acc[TDIM];
    #pragma unroll
    for (int t = 0; t < TDIM; t++) acc[t] = 0.f;
    for (int nl = 0; nl < 512; nl++) {
        float h = g_H2[(size_t)(n0 + nl) * H2DIM + col];
        #pragma unroll
        for (int t = 0; t < TDIM; t++) acc[t] += bsh[t * 512 + nl] * h;
    }
    #pragma unroll
    for (int t = 0; t < TDIM; t++)
        g_embs_part[(size_t)(s * TDIM + t) * H2DIM + col] = acc[t];
}

// ---------------- final ----------------
__global__ void final_kernel(const float* __restrict__ glob_w1, const float* __restrict__ glob_b1,
                             const float* __restrict__ glob_w2, const float* __restrict__ glob_b2,
                             const float* __restrict__ cls_w,  const float* __restrict__ cls_b,
                             float* __restrict__ out, int out_size) {
    __shared__ float esh[TDIM * H2DIM];
    __shared__ float vsh[1280];
    __shared__ float gam[TDIM];
    __shared__ float psh[2];
    int tid = threadIdx.x;

    for (int i = tid; i < TDIM * H2DIM; i += 256) {
        float s = 0.f;
        #pragma unroll
        for (int p = 0; p < NSPLIT; p++) s += g_embs_part[(size_t)p * TDIM * H2DIM + i];
        esh[i] = s;
    }
    __syncthreads();

    for (int idx = tid; idx < TDIM * 128; idx += 256) {
        int t = idx >> 7, j = idx & 127;
        const float* w = glob_w1 + (size_t)j * H2DIM;
        const float* e = esh + t * H2DIM;
        float s = glob_b1[j];
        for (int k = 0; k < H2DIM; k++) s += w[k] * e[k];
        vsh[idx] = tanhf(s);
    }
    __syncthreads();

    if (tid < TDIM) {
        float s = glob_b2[0];
        for (int j = 0; j < 128; j++) s += glob_w2[j] * vsh[tid * 128 + j];
        gam[tid] = s;
    }
    __syncthreads();
    if (tid == 0) {
        float m = gam[0];
        for (int t = 1; t < TDIM; t++) m = fmaxf(m, gam[t]);
        float ss = 0.f;
        for (int t = 0; t < TDIM; t++) { gam[t] = expf(gam[t] - m); ss += gam[t]; }
        float inv = 1.f / ss;
        for (int t = 0; t < TDIM; t++) gam[t] *= inv;
    }
    __syncthreads();

    float* Msh = vsh;
    for (int k = tid; k < H2DIM; k += 256) {
        float s = 0.f;
        #pragma unroll
        for (int t = 0; t < TDIM; t++) s += gam[t] * esh[t * H2DIM + k];
        Msh[k] = s;
    }
    __syncthreads();

    if (tid < 64) {
        int c = tid >> 5, lane = tid & 31;
        float s = 0.f;
        for (int k = lane; k < H2DIM; k += 32) s += cls_w[(size_t)c * H2DIM + k] * Msh[k];
        #pragma unroll
        for (int o = 16; o; o >>= 1) s += __shfl_xor_sync(0xffffffffu, s, o);
        if (lane == 0) {
            float p = 1.f / (1.f + expf(-(s + cls_b[c])));
            psh[c] = p;
            if (c < out_size) out[c] = p;
        }
    }
    __syncthreads();
    if (tid == 0 && out_size > 2) out[2] = (psh[1] > psh[0]) ? 1.0f : 0.0f;

    for (int n = tid; n < NN; n += 256) {
        float s = 0.f;
        #pragma unroll
        for (int t = 0; t < TDIM; t++) s += gam[t] * g_betas[t * NN + n];
        if (3 + n < out_size) out[3 + n] = s;
    }
}

// ---------------- launch ----------------
extern "C" void kernel_launch(void* const* d_in, const int* in_sizes, int n_in,
                              void* d_out, int out_size) {
    const float* x        = (const float*)d_in[0];
    const float* conv1_w  = (const float*)d_in[2];
    const float* conv1_b  = (const float*)d_in[3];
    const float* conv2_w  = (const float*)d_in[4];
    const float* conv2_b  = (const float*)d_in[5];
    const float* fc1_w    = (const float*)d_in[6];
    const float* fc1_b    = (const float*)d_in[7];
    const float* fc2_w    = (const float*)d_in[8];
    const float* fc2_b    = (const float*)d_in[9];
    const float* nbr_w    = (const float*)d_in[10];
    const float* nbr_b    = (const float*)d_in[11];
    const float* templates= (const float*)d_in[12];
    const float* proto_w  = (const float*)d_in[13];
    const float* proto_b  = (const float*)d_in[14];
    const float* glob_w1  = (const float*)d_in[15];
    const float* glob_b1  = (const float*)d_in[16];
    const float* glob_w2  = (const float*)d_in[17];
    const float* glob_b2  = (const float*)d_in[18];
    const float* cls_w    = (const float*)d_in[19];
    const float* cls_b    = (const float*)d_in[20];
    float* out = (float*)d_out;

    float *H2, *An, *P;
    __nv_bfloat16 *H0s, *H1s, *H2s, *fc1ws, *fc2ws, *nbrws, *protows;
    cudaGetSymbolAddress((void**)&H2, g_H2);
    cudaGetSymbolAddress((void**)&An, g_An);
    cudaGetSymbolAddress((void**)&P,  g_P);
    cudaGetSymbolAddress((void**)&H0s, g_H0s);
    cudaGetSymbolAddress((void**)&H1s, g_H1s);
    cudaGetSymbolAddress((void**)&H2s, g_H2s);
    cudaGetSymbolAddress((void**)&fc1ws, g_fc1ws);
    cudaGetSymbolAddress((void**)&fc2ws, g_fc2ws);
    cudaGetSymbolAddress((void**)&nbrws, g_nbrws);
    cudaGetSymbolAddress((void**)&protows, g_protows);

    const size_t conv_smem = S_TOTALF * sizeof(float);
    cudaFuncSetAttribute(conv_fused_kernel, cudaFuncAttributeMaxDynamicSharedMemorySize, (int)conv_smem);
    const int gsmem = 49152;
    cudaFuncSetAttribute(mma_gemm<1, false, true>,  cudaFuncAttributeMaxDynamicSharedMemorySize, gsmem);
    cudaFuncSetAttribute(mma_gemm<1, true,  true>,  cudaFuncAttributeMaxDynamicSharedMemorySize, gsmem);
    cudaFuncSetAttribute(mma_gemm<2, true,  false>, cudaFuncAttributeMaxDynamicSharedMemorySize, gsmem);

    // 3 noops: capture = 5th launch overall (1 harness pre-launch + 3 noops) -> conv_fused
    for (int i = 0; i < 3; i++) noop_kernel<<<1, 32>>>();

    conv_fused_kernel<<<NN, 512, conv_smem>>>(x, conv1_w, conv1_b, conv2_w, conv2_b);

    cvt_w_kernel<<<(HDIM * H0DIM + 255) / 256, 256>>>(fc1_w, fc1ws, H0DIM, HDIM * H0DIM);
    cvt_w_kernel<<<(HDIM * HDIM + 255) / 256, 256>>>(fc2_w, fc2ws, HDIM, HDIM * HDIM);
    cvt_w_kernel<<<(HDIM * HDIM + 255) / 256, 256>>>(nbr_w, nbrws, HDIM, HDIM * HDIM);
    cvt_w_kernel<<<(H2DIM * H2DIM + 255) / 256, 256>>>(proto_w, protows, H2DIM, H2DIM * H2DIM);

    mma_gemm<1, false, true><<<dim3(HDIM / 64, NN / 128), 256, gsmem>>>(
        H0s, fc1ws, fc1_b, nullptr, H1s, H0DIM, 3 * H0DIM, H0DIM, 3 * H0DIM, H0DIM, 0, 3 * HDIM, HDIM);
    mma_gemm<1, true, true><<<dim3(HDIM / 64, NN / 128), 256, gsmem>>>(
        H1s, fc2ws, fc2_b, H2, H2s, HDIM, 3 * HDIM, HDIM, 3 * HDIM, HDIM, H2DIM, 3 * H2DIM, H2DIM);
    mma_gemm<2, true, false><<<dim3(HDIM / 64, NN / 128), 256, gsmem>>>(
        H2s, nbrws, nbr_b, An, nullptr, HDIM, 3 * H2DIM, H2DIM, 3 * HDIM, HDIM, HDIM, 0, 0);
    nbr_kernel<<<NN / 8, 256>>>();
    mma_gemm<2, true, false><<<dim3(H2DIM / 64, NN / 128), 256, gsmem>>>(
        H2s, protows, proto_b, P, nullptr, H2DIM, 3 * H2DIM, H2DIM, 3 * H2DIM, H2DIM, H2DIM, 0, 0);

    tlogits_kernel<<<NN, 320>>>(templates);
    betas_kernel<<<TDIM, 256>>>();
    embs_part_kernel<<<dim3(H2DIM / 128, NSPLIT), 128>>>();
    final_kernel<<<1, 256>>>(glob_w1, glob_b1, glob_w2, glob_b2, cls_w, cls_b, out, out_size);
}

// round 7
// speedup vs baseline: 3.0474x; 2.5564x over previous
#include <cuda_runtime.h>
#include <cuda_bf16.h>
#include <math.h>

typedef unsigned long long ull;
typedef unsigned int u32;

// ---------------- problem constants ----------------
#define NN        2048
#define P1        14
#define H0DIM     1728
#define HDIM      512
#define H2DIM     1024
#define TDIM      10
#define NSPLIT    16

// conv SMEM layout (floats)
#define S_IMG     0                       // 32x33 = 1056
#define S_W1      1056                    // 576
#define S_B1      1632                    // 36
#define S_B2      1668                    // 48
#define S_POOL1   1716                    // 7056
#define S_W2      8772                    // 324 rows * stride 50 = 16200 (reused as out, stride 49)
#define S_TOTALF  (8772 + 16200)          // 24972 floats = 99888 B

#define W2STRIDE  50

#define SWZ(off)  ((off) ^ (((off) >> 3) & 0x70))

// ---------------- scratch ----------------
__device__ float g_H2[(size_t)NN * H2DIM];
__device__ float g_An[(size_t)NN * HDIM];
__device__ float g_P[(size_t)NN * H2DIM];
__device__ float g_L[TDIM * NN];                          // transposed: [t][n]
__device__ float g_betas[TDIM * NN];
__device__ float g_embs_part[NSPLIT * TDIM * H2DIM];
__device__ float g_embs[TDIM * H2DIM];
__device__ float g_V[TDIM * 128];

// bf16 split buffers (A-side rows: [hi|hi|lo], B-side weight rows: [hi|lo|hi])
__device__ __align__(256) __nv_bfloat16 g_H0s[(size_t)NN * 3 * H0DIM];
__device__ __align__(256) __nv_bfloat16 g_H1s[(size_t)NN * 3 * HDIM];
__device__ __align__(256) __nv_bfloat16 g_H2s[(size_t)NN * 3 * H2DIM];
__device__ __align__(256) __nv_bfloat16 g_fc1ws[(size_t)HDIM * 3 * H0DIM];
__device__ __align__(256) __nv_bfloat16 g_fc2ws[(size_t)HDIM * 3 * HDIM];
__device__ __align__(256) __nv_bfloat16 g_nbrws[(size_t)HDIM * 3 * HDIM];
__device__ __align__(256) __nv_bfloat16 g_protows[(size_t)H2DIM * 3 * H2DIM];

__global__ void noop_kernel() {}

__device__ __forceinline__ u32 smem_u32(const void* p) {
    u32 a; asm("{ .reg .u64 t; cvta.to.shared.u64 t, %1; cvt.u32.u64 %0, t; }" : "=r"(a) : "l"(p));
    return a;
}
__device__ __forceinline__ void cp16(u32 dst, const void* src) {
    asm volatile("cp.async.ca.shared.global [%0], [%1], 16;" :: "r"(dst), "l"(src));
}
__device__ __forceinline__ void cp_commit() { asm volatile("cp.async.commit_group;" ::: "memory"); }
template <int N>
__device__ __forceinline__ void cp_wait() { asm volatile("cp.async.wait_group %0;" :: "n"(N) : "memory"); }

// ---------------- weight split cvt: w[N,K] fp32 -> [hi|lo|hi] bf16 ----------------
__global__ void cvt_w_kernel(const float* __restrict__ w, __nv_bfloat16* __restrict__ o, int K, int total) {
    int idx = blockIdx.x * 256 + threadIdx.x;
    if (idx >= total) return;
    int n = idx / K, k = idx - n * K;
    float v = w[idx];
    __nv_bfloat16 hi = __float2bfloat16(v);
    __nv_bfloat16 lo = __float2bfloat16(v - __bfloat162float(hi));
    size_t base = (size_t)n * 3 * K + k;
    o[base] = hi; o[base + K] = lo; o[base + 2 * K] = hi;
}

// ---------------- fused conv1+pool1+conv2+pool2 ----------------
__device__ __forceinline__ ull pack2(float lo, float hi) {
    ull r; asm("mov.b64 %0, {%1, %2};" : "=l"(r) : "f"(lo), "f"(hi)); return r;
}
__device__ __forceinline__ void unpack2(ull v, float& lo, float& hi) {
    asm("mov.b64 {%0, %1}, %2;" : "=f"(lo), "=f"(hi) : "l"(v));
}
__device__ __forceinline__ void fma2(ull& d, ull a, ull b) {
    asm("fma.rn.f32x2 %0, %1, %2, %0;" : "+l"(d) : "l"(a), "l"(b));
}

__global__ __launch_bounds__(512, 2)
void conv_fused_kernel(const float* __restrict__ x,
                       const float* __restrict__ w1,
                       const float* __restrict__ b1,
                       const float* __restrict__ w2,
                       const float* __restrict__ b2) {
    extern __shared__ float sm[];
    float* s_img   = sm + S_IMG;
    float* s_w1    = sm + S_W1;
    float* s_b1    = sm + S_B1;
    float* s_b2    = sm + S_B2;
    float* s_pool1 = sm + S_POOL1;
    float* s_w2    = sm + S_W2;

    int n = blockIdx.x, tid = threadIdx.x;
    const float* xin = x + (size_t)n * 1024;

    for (int i = tid; i < 1024; i += 512) {
        int r = i >> 5, c = i & 31;
        s_img[r * 33 + c] = xin[i];
    }
    for (int i = tid; i < 576; i += 512) s_w1[i] = w1[i];
    if (tid < 36) s_b1[tid] = b1[tid];
    else if (tid >= 64 && tid < 112) s_b2[tid - 64] = b2[tid - 64];
    for (int i = tid; i < 15552; i += 512) {
        int ch = i / 324, r = i - ch * 324;
        s_w2[r * W2STRIDE + ch] = w2[i];
    }
    __syncthreads();

    // --- conv1 + relu + pool: row-accumulation ---
    if (tid < 504) {
        int ch = tid / 14, py = tid % 14;
        const float4* wp = (const float4*)&s_w1[ch * 16];
        float4 a0 = wp[0], a1 = wp[1], a2 = wp[2], a3 = wp[3];
        float wr[16] = {a0.x,a0.y,a0.z,a0.w, a1.x,a1.y,a1.z,a1.w,
                        a2.x,a2.y,a2.z,a2.w, a3.x,a3.y,a3.z,a3.w};
        float bias1 = s_b1[ch];
        float* prow = s_pool1 + ch * 196 + py * 14;
        const float* ibase = s_img + (2 * py) * 33;
        for (int px = 0; px < 14; px++) {
            float s00 = 0.f, s01 = 0.f, s10 = 0.f, s11 = 0.f;
            const float* ip = ibase + 2 * px;
            #pragma unroll
            for (int yy = 0; yy < 5; yy++) {
                float r0 = ip[yy * 33 + 0], r1 = ip[yy * 33 + 1], r2 = ip[yy * 33 + 2];
                float r3 = ip[yy * 33 + 3], r4 = ip[yy * 33 + 4];
                if (yy <= 3) {
                    const float* w = wr + yy * 4;
                    s00 += r0 * w[0] + r1 * w[1] + r2 * w[2] + r3 * w[3];
                    s01 += r1 * w[0] + r2 * w[1] + r3 * w[2] + r4 * w[3];
                }
                if (yy >= 1) {
                    const float* w = wr + (yy - 1) * 4;
                    s10 += r0 * w[0] + r1 * w[1] + r2 * w[2] + r3 * w[3];
                    s11 += r1 * w[0] + r2 * w[1] + r3 * w[2] + r4 * w[3];
                }
            }
            float m = fmaxf(fmaxf(s00, s01), fmaxf(s10, s11));
            prow[px] = fmaxf(m + bias1, 0.f);
        }
    }
    __syncthreads();

    // --- conv2: thread = (16-ch group g, position PAIR q/q+72); 2x weight reuse ---
    ull acc0[8], acc1[8];
    int g = tid / 72, q = tid - g * 72;
    if (tid < 216) {
        int cy = q / 12, cx = q - cy * 12;
        #pragma unroll
        for (int j = 0; j < 8; j++) { acc0[j] = 0ull; acc1[j] = 0ull; }
        const float* in0 = s_pool1 + cy * 14 + cx;
        const float* in1 = in0 + 84;              // position q+72 -> cy+6, same cx
        const float* wgb = s_w2 + g * 16;
        for (int c = 0; c < 36; c++) {
            #pragma unroll
            for (int k = 0; k < 9; k++) {
                int ioff = c * 196 + (k / 3) * 14 + (k % 3);
                float v0 = in0[ioff], v1 = in1[ioff];
                ull vv0 = pack2(v0, v0), vv1 = pack2(v1, v1);
                const ull* qw = (const ull*)(wgb + (c * 9 + k) * W2STRIDE);
                #pragma unroll
                for (int j = 0; j < 8; j++) {
                    ull w = qw[j];
                    fma2(acc0[j], w, vv0);
                    fma2(acc1[j], w, vv1);
                }
            }
        }
    }
    __syncthreads();   // weights done -> reuse s_w2 region as out buffer (stride 49)
    if (tid < 216) {
        float* o0 = s_w2 + q * 49 + g * 16;
        float* o1 = s_w2 + (q + 72) * 49 + g * 16;
        #pragma unroll
        for (int j = 0; j < 8; j++) {
            float lo, hi;
            unpack2(acc0[j], lo, hi); o0[2 * j] = lo; o0[2 * j + 1] = hi;
            unpack2(acc1[j], lo, hi); o1[2 * j] = lo; o1[2 * j + 1] = hi;
        }
    }
    __syncthreads();

    __nv_bfloat16* outb = g_H0s + (size_t)n * 3 * H0DIM;
    for (int o = tid; o < 1728; o += 512) {
        int ch = o / 36, pp = o - ch * 36;
        int py = pp / 6, px = pp - py * 6;
        int i00 = (2 * py) * 12 + 2 * px;
        float m = fmaxf(fmaxf(s_w2[i00 * 49 + ch],        s_w2[(i00 + 1)  * 49 + ch]),
                        fmaxf(s_w2[(i00 + 12) * 49 + ch], s_w2[(i00 + 13) * 49 + ch]));
        float v = fmaxf(m + s_b2[ch], 0.f);
        __nv_bfloat16 hi = __float2bfloat16(v);
        __nv_bfloat16 lo = __float2bfloat16(v - __bfloat162float(hi));
        outb[o] = hi; outb[1728 + o] = hi; outb[3456 + o] = lo;
    }
}

// ---------------- mma.sync bf16 GEMM (cp.async double buffer) ----------------
template <int ACT, bool WF, bool WS>
__global__ __launch_bounds__(256)
void mma_gemm(const __nv_bfloat16* __restrict__ A, const __nv_bfloat16* __restrict__ B,
              const float* __restrict__ bias, float* __restrict__ Cf, __nv_bfloat16* __restrict__ Cs,
              int K, int rsA, int ssA, int rsB, int ssB, int ldc, int ldcs, int slotC) {
    extern __shared__ char smem[];
    u32 sb = smem_u32(smem);
    const int tid = threadIdx.x, wid = tid >> 5, lane = tid & 31;
    const int bm = blockIdx.y * 128, bn = blockIdx.x * 64;
    const int wm = wid & 1, wn = wid >> 1;
    const int lr = tid >> 3, lg = tid & 7;

    auto cp_tile = [&](int kc, int buf) {
        int slot = kc / K, off = kc - slot * K;
        const __nv_bfloat16* Ab = A + (size_t)bm * rsA + (size_t)slot * ssA + off;
        u32 pA = sb + buf * 24576;
        #pragma unroll
        for (int i = 0; i < 4; i++)
            cp16(pA + SWZ((lr + i * 32) * 128 + lg * 16), Ab + (size_t)(lr + i * 32) * rsA + lg * 8);
        const __nv_bfloat16* Bb = B + (size_t)bn * rsB + (size_t)slot * ssB + off;
        u32 pB = sb + buf * 24576 + 16384;
        #pragma unroll
        for (int i = 0; i < 2; i++)
            cp16(pB + SWZ((lr + i * 32) * 128 + lg * 16), Bb + (size_t)(lr + i * 32) * rsB + lg * 8);
    };

    float acc[4][2][4];
    #pragma unroll
    for (int mi = 0; mi < 4; mi++)
        #pragma unroll
        for (int ni = 0; ni < 2; ni++)
            #pragma unroll
            for (int j = 0; j < 4; j++) acc[mi][ni][j] = 0.f;

    const int nch = (3 * K) / 64;
    cp_tile(0, 0); cp_commit();

    for (int c = 0; c < nch; c++) {
        int buf = c & 1;
        if (c + 1 < nch) { cp_tile((c + 1) * 64, buf ^ 1); cp_commit(); cp_wait<1>(); }
        else cp_wait<0>();
        __syncthreads();
        u32 sA = sb + buf * 24576, sBB = sb + buf * 24576 + 16384;
        #pragma unroll
        for (int ks = 0; ks < 4; ks++) {
            u32 a[4][4], b[2][2];
            #pragma unroll
            for (int mi = 0; mi < 4; mi++) {
                int row = wm * 64 + mi * 16 + (lane & 15);
                int gq = ks * 2 + (lane >> 4);
                u32 ad = sA + SWZ(row * 128 + gq * 16);
                asm volatile("ldmatrix.sync.aligned.m8n8.x4.shared.b16 {%0,%1,%2,%3}, [%4];"
                             : "=r"(a[mi][0]), "=r"(a[mi][1]), "=r"(a[mi][2]), "=r"(a[mi][3]) : "r"(ad));
            }
            #pragma unroll
            for (int ni = 0; ni < 2; ni++) {
                int row = wn * 16 + ni * 8 + (lane & 7);
                int gq = ks * 2 + ((lane >> 3) & 1);
                u32 ad = sBB + SWZ(row * 128 + gq * 16);
                asm volatile("ldmatrix.sync.aligned.m8n8.x2.shared.b16 {%0,%1}, [%2];"
                             : "=r"(b[ni][0]), "=r"(b[ni][1]) : "r"(ad));
            }
            #pragma unroll
            for (int mi = 0; mi < 4; mi++)
                #pragma unroll
                for (int ni = 0; ni < 2; ni++)
                    asm volatile("mma.sync.aligned.m16n8k16.row.col.f32.bf16.bf16.f32 "
                                 "{%0,%1,%2,%3}, {%4,%5,%6,%7}, {%8,%9}, {%0,%1,%2,%3};"
                                 : "+f"(acc[mi][ni][0]), "+f"(acc[mi][ni][1]),
                                   "+f"(acc[mi][ni][2]), "+f"(acc[mi][ni][3])
                                 : "r"(a[mi][0]), "r"(a[mi][1]), "r"(a[mi][2]), "r"(a[mi][3]),
                                   "r"(b[ni][0]), "r"(b[ni][1]));
        }
        __syncthreads();
    }

    #pragma unroll
    for (int ni = 0; ni < 2; ni++) {
        int c0 = bn + wn * 16 + ni * 8 + (lane & 3) * 2;
        float b0 = bias[c0], b1 = bias[c0 + 1];
        #pragma unroll
        for (int mi = 0; mi < 4; mi++) {
            int r0 = bm + wm * 64 + mi * 16 + (lane >> 2);
            float v0 = acc[mi][ni][0] + b0, v1 = acc[mi][ni][1] + b1;
            float v2 = acc[mi][ni][2] + b0, v3 = acc[mi][ni][3] + b1;
            if (ACT == 1) { v0 = fmaxf(v0, 0.f); v1 = fmaxf(v1, 0.f); v2 = fmaxf(v2, 0.f); v3 = fmaxf(v3, 0.f); }
            if (ACT == 2) { v0 = tanhf(v0); v1 = tanhf(v1); v2 = tanhf(v2); v3 = tanhf(v3); }
            if (WF) {
                *(float2*)(Cf + (size_t)r0 * ldc + c0)       = make_float2(v0, v1);
                *(float2*)(Cf + (size_t)(r0 + 8) * ldc + c0) = make_float2(v2, v3);
            }
            if (WS) {
                __nv_bfloat16* s0 = Cs + (size_t)r0 * ldcs + c0;
                __nv_bfloat16* s1 = Cs + (size_t)(r0 + 8) * ldcs + c0;
                float vv[2][2] = {{v0, v1}, {v2, v3}};
                __nv_bfloat16* sp[2] = {s0, s1};
                #pragma unroll
                for (int rr = 0; rr < 2; rr++)
                    #pragma unroll
                    for (int jj = 0; jj < 2; jj++) {
                        float v = vv[rr][jj];
                        __nv_bfloat16 hi = __float2bfloat16(v);
                        __nv_bfloat16 lo = __float2bfloat16(v - __bfloat162float(hi));
                        sp[rr][jj] = hi; sp[rr][slotC + jj] = hi; sp[rr][2 * slotC + jj] = lo;
                    }
            }
        }
    }
}

// ---------------- neighborhood attention (one warp per node) ----------------
__global__ void nbr_kernel() {
    int gwarp = (blockIdx.x * blockDim.x + threadIdx.x) >> 5;
    int lane = threadIdx.x & 31;
    if (gwarp >= NN) return;
    int i = gwarp;
    int r = i >> 6, c = i & 63;

    float hi[16];
    const float* Hi = g_H2 + (size_t)i * H2DIM;
    #pragma unroll
    for (int u = 0; u < 16; u++) hi[u] = Hi[lane + 32 * u];

    int nbrs[8]; int cnt = 0;
    for (int dr = -1; dr <= 1; dr++)
        for (int dc = -1; dc <= 1; dc++) {
            if (dr == 0 && dc == 0) continue;
            int rr = r + dr, cc = c + dc;
            if (rr >= 0 && rr < 32 && cc >= 0 && cc < 64) nbrs[cnt++] = rr * 64 + cc;
        }

    float dots[8];
    for (int q = 0; q < cnt; q++) {
        const float* An = g_An + (size_t)nbrs[q] * HDIM;
        float s = 0.f;
        #pragma unroll
        for (int u = 0; u < 16; u++) s += hi[u] * An[lane + 32 * u];
        #pragma unroll
        for (int o = 16; o; o >>= 1) s += __shfl_xor_sync(0xffffffffu, s, o);
        dots[q] = s;
    }
    float m = -3.0e38f;
    for (int q = 0; q < cnt; q++) m = fmaxf(m, dots[q]);
    float ssum = 0.f;
    for (int q = 0; q < cnt; q++) { dots[q] = expf(dots[q] - m); ssum += dots[q]; }
    float inv = 1.f / ssum;

    float accv[16];
    #pragma unroll
    for (int u = 0; u < 16; u++) accv[u] = 0.f;
    for (int q = 0; q < cnt; q++) {
        float a = dots[q] * inv;
        const float* Hj = g_H2 + (size_t)nbrs[q] * H2DIM;
        #pragma unroll
        for (int u = 0; u < 16; u++) accv[u] += a * Hj[lane + 32 * u];
    }
    float* o = g_H2 + (size_t)i * H2DIM + HDIM;
    __nv_bfloat16* os = g_H2s + (size_t)i * 3 * H2DIM;
    #pragma unroll
    for (int u = 0; u < 16; u++) {
        float v = accv[u];
        int col = 512 + lane + 32 * u;
        o[lane + 32 * u] = v;
        __nv_bfloat16 vh = __float2bfloat16(v);
        __nv_bfloat16 vl = __float2bfloat16(v - __bfloat162float(vh));
        os[col] = vh; os[1024 + col] = vh; os[2048 + col] = vl;
    }
}

// ---------------- template logits (transposed out) ----------------
__global__ void tlogits_kernel(const float* __restrict__ templates) {
    int n = blockIdx.x;
    int t = threadIdx.x >> 5, lane = threadIdx.x & 31;
    const float* p = g_P + (size_t)n * H2DIM;
    const float* tm = templates + (size_t)t * H2DIM;
    float s = 0.f;
    for (int k = lane; k < H2DIM; k += 32) s += p[k] * tm[k];
    #pragma unroll
    for (int o = 16; o; o >>= 1) s += __shfl_xor_sync(0xffffffffu, s, o);
    if (lane == 0) g_L[t * NN + n] = s;
}

// ---------------- betas softmax (coalesced reads) ----------------
__global__ void betas_kernel() {
    int t = blockIdx.x, tid = threadIdx.x;
    __shared__ float red[256];
    __shared__ float smax, ssum;
    const float* L = g_L + t * NN;
    float m = -3.0e38f;
    for (int n = tid; n < NN; n += 256) m = fmaxf(m, L[n]);
    red[tid] = m; __syncthreads();
    for (int s = 128; s; s >>= 1) { if (tid < s) red[tid] = fmaxf(red[tid], red[tid + s]); __syncthreads(); }
    if (tid == 0) smax = red[0];
    __syncthreads();
    float acc = 0.f;
    for (int n = tid; n < NN; n += 256) acc += expf(L[n] - smax);
    red[tid] = acc; __syncthreads();
    for (int s = 128; s; s >>= 1) { if (tid < s) red[tid] += red[tid + s]; __syncthreads(); }
    if (tid == 0) ssum = 1.f / red[0];
    __syncthreads();
    for (int n = tid; n < NN; n += 256)
        g_betas[t * NN + n] = expf(L[n] - smax) * ssum;
}

// ---------------- embs partials (128-row chunks, 128 blocks) ----------------
__global__ void embs_part_kernel() {
    __shared__ float bsh[TDIM * 128];
    int col = blockIdx.x * 128 + threadIdx.x;
    int s = blockIdx.y;
    int n0 = s * 128;
    for (int i = threadIdx.x; i < TDIM * 128; i += 128) {
        int t = i >> 7, nl = i & 127;
        bsh[i] = g_betas[t * NN + n0 + nl];
    }
    __syncthreads();
    float acc[TDIM];
    #pragma unroll
    for (int t = 0; t < TDIM; t++) acc[t] = 0.f;
    for (int nl = 0; nl < 128; nl++) {
        float h = g_H2[(size_t)(n0 + nl) * H2DIM + col];
        #pragma unroll
        for (int t = 0; t < TDIM; t++) acc[t] += bsh[t * 128 + nl] * h;
    }
    #pragma unroll
    for (int t = 0; t < TDIM; t++)
        g_embs_part[(size_t)(s * TDIM + t) * H2DIM + col] = acc[t];
}

__global__ void embs_reduce_kernel() {
    int i = blockIdx.x * 256 + threadIdx.x;
    if (i >= TDIM * H2DIM) return;
    float s = 0.f;
    #pragma unroll
    for (int p = 0; p < NSPLIT; p++) s += g_embs_part[(size_t)p * TDIM * H2DIM + i];
    g_embs[i] = s;
}

// ---------------- glob1: V[t][j] = tanh(glob_w1[j] . embs[t] + b1[j]) ----------------
__global__ void glob1_kernel(const float* __restrict__ glob_w1, const float* __restrict__ glob_b1) {
    int t = blockIdx.y;
    int w = threadIdx.x >> 5, lane = threadIdx.x & 31;
    int j = blockIdx.x * 8 + w;           // grid.x = 16 -> j in 0..127
    const float* wr = glob_w1 + (size_t)j * H2DIM;
    const float* e = g_embs + t * H2DIM;
    float s = 0.f;
    #pragma unroll 8
    for (int k = lane; k < H2DIM; k += 32) s += wr[k] * e[k];
    #pragma unroll
    for (int o = 16; o; o >>= 1) s += __shfl_xor_sync(0xffffffffu, s, o);
    if (lane == 0) g_V[t * 128 + j] = tanhf(s + glob_b1[j]);
}

// ---------------- final2: gammas, M, classifier, A ----------------
__global__ void final2_kernel(const float* __restrict__ glob_w2, const float* __restrict__ glob_b2,
                              const float* __restrict__ cls_w,  const float* __restrict__ cls_b,
                              float* __restrict__ out, int out_size) {
    __shared__ float vsh[TDIM * 128];
    __shared__ float Msh[H2DIM];
    __shared__ float gam[TDIM];
    __shared__ float psh[2];
    int tid = threadIdx.x;  // 256

    for (int i = tid; i < TDIM * 128; i += 256) vsh[i] = g_V[i];
    __syncthreads();

    if (tid < TDIM) {
        float s = glob_b2[0];
        for (int j = 0; j < 128; j++) s += glob_w2[j] * vsh[tid * 128 + j];
        gam[tid] = s;
    }
    __syncthreads();
    if (tid == 0) {
        float m = gam[0];
        for (int t = 1; t < TDIM; t++) m = fmaxf(m, gam[t]);
        float ss = 0.f;
        for (int t = 0; t < TDIM; t++) { gam[t] = expf(gam[t] - m); ss += gam[t]; }
        float inv = 1.f / ss;
        for (int t = 0; t < TDIM; t++) gam[t] *= inv;
    }
    __syncthreads();

    for (int k = tid; k < H2DIM; k += 256) {
        float s = 0.f;
        #pragma unroll
        for (int t = 0; t < TDIM; t++) s += gam[t] * g_embs[t * H2DIM + k];
        Msh[k] = s;
    }
    __syncthreads();

    if (tid < 64) {
        int c = tid >> 5, lane = tid & 31;
        float s = 0.f;
        for (int k = lane; k < H2DIM; k += 32) s += cls_w[(size_t)c * H2DIM + k] * Msh[k];
        #pragma unroll
        for (int o = 16; o; o >>= 1) s += __shfl_xor_sync(0xffffffffu, s, o);
        if (lane == 0) {
            float p = 1.f / (1.f + expf(-(s + cls_b[c])));
            psh[c] = p;
            if (c < out_size) out[c] = p;
        }
    }
    __syncthreads();
    if (tid == 0 && out_size > 2) out[2] = (psh[1] > psh[0]) ? 1.0f : 0.0f;

    for (int n = tid; n < NN; n += 256) {
        float s = 0.f;
        #pragma unroll
        for (int t = 0; t < TDIM; t++) s += gam[t] * g_betas[t * NN + n];
        if (3 + n < out_size) out[3 + n] = s;
    }
}

// ---------------- launch ----------------
extern "C" void kernel_launch(void* const* d_in, const int* in_sizes, int n_in,
                              void* d_out, int out_size) {
    const float* x        = (const float*)d_in[0];
    const float* conv1_w  = (const float*)d_in[2];
    const float* conv1_b  = (const float*)d_in[3];
    const float* conv2_w  = (const float*)d_in[4];
    const float* conv2_b  = (const float*)d_in[5];
    const float* fc1_w    = (const float*)d_in[6];
    const float* fc1_b    = (const float*)d_in[7];
    const float* fc2_w    = (const float*)d_in[8];
    const float* fc2_b    = (const float*)d_in[9];
    const float* nbr_w    = (const float*)d_in[10];
    const float* nbr_b    = (const float*)d_in[11];
    const float* templates= (const float*)d_in[12];
    const float* proto_w  = (const float*)d_in[13];
    const float* proto_b  = (const float*)d_in[14];
    const float* glob_w1  = (const float*)d_in[15];
    const float* glob_b1  = (const float*)d_in[16];
    const float* glob_w2  = (const float*)d_in[17];
    const float* glob_b2  = (const float*)d_in[18];
    const float* cls_w    = (const float*)d_in[19];
    const float* cls_b    = (const float*)d_in[20];
    float* out = (float*)d_out;

    float *H2, *An, *P;
    __nv_bfloat16 *H0s, *H1s, *H2s, *fc1ws, *fc2ws, *nbrws, *protows;
    cudaGetSymbolAddress((void**)&H2, g_H2);
    cudaGetSymbolAddress((void**)&An, g_An);
    cudaGetSymbolAddress((void**)&P,  g_P);
    cudaGetSymbolAddress((void**)&H0s, g_H0s);
    cudaGetSymbolAddress((void**)&H1s, g_H1s);
    cudaGetSymbolAddress((void**)&H2s, g_H2s);
    cudaGetSymbolAddress((void**)&fc1ws, g_fc1ws);
    cudaGetSymbolAddress((void**)&fc2ws, g_fc2ws);
    cudaGetSymbolAddress((void**)&nbrws, g_nbrws);
    cudaGetSymbolAddress((void**)&protows, g_protows);

    const size_t conv_smem = S_TOTALF * sizeof(float);
    cudaFuncSetAttribute(conv_fused_kernel, cudaFuncAttributeMaxDynamicSharedMemorySize, (int)conv_smem);
    const int gsmem = 49152;
    cudaFuncSetAttribute(mma_gemm<1, false, true>,  cudaFuncAttributeMaxDynamicSharedMemorySize, gsmem);
    cudaFuncSetAttribute(mma_gemm<1, true,  true>,  cudaFuncAttributeMaxDynamicSharedMemorySize, gsmem);
    cudaFuncSetAttribute(mma_gemm<2, true,  false>, cudaFuncAttributeMaxDynamicSharedMemorySize, gsmem);

    // 3 noops: capture = 5th launch overall -> conv_fused
    for (int i = 0; i < 3; i++) noop_kernel<<<1, 32>>>();

    conv_fused_kernel<<<NN, 512, conv_smem>>>(x, conv1_w, conv1_b, conv2_w, conv2_b);

    cvt_w_kernel<<<(HDIM * H0DIM + 255) / 256, 256>>>(fc1_w, fc1ws, H0DIM, HDIM * H0DIM);
    cvt_w_kernel<<<(HDIM * HDIM + 255) / 256, 256>>>(fc2_w, fc2ws, HDIM, HDIM * HDIM);
    cvt_w_kernel<<<(HDIM * HDIM + 255) / 256, 256>>>(nbr_w, nbrws, HDIM, HDIM * HDIM);
    cvt_w_kernel<<<(H2DIM * H2DIM + 255) / 256, 256>>>(proto_w, protows, H2DIM, H2DIM * H2DIM);

    mma_gemm<1, false, true><<<dim3(HDIM / 64, NN / 128), 256, gsmem>>>(
        H0s, fc1ws, fc1_b, nullptr, H1s, H0DIM, 3 * H0DIM, H0DIM, 3 * H0DIM, H0DIM, 0, 3 * HDIM, HDIM);
    mma_gemm<1, true, true><<<dim3(HDIM / 64, NN / 128), 256, gsmem>>>(
        H1s, fc2ws, fc2_b, H2, H2s, HDIM, 3 * HDIM, HDIM, 3 * HDIM, HDIM, H2DIM, 3 * H2DIM, H2DIM);
    mma_gemm<2, true, false><<<dim3(HDIM / 64, NN / 128), 256, gsmem>>>(
        H2s, nbrws, nbr_b, An, nullptr, HDIM, 3 * H2DIM, H2DIM, 3 * HDIM, HDIM, HDIM, 0, 0);
    nbr_kernel<<<NN / 8, 256>>>();
    mma_gemm<2, true, false><<<dim3(H2DIM / 64, NN / 128), 256, gsmem>>>(
        H2s, protows, proto_b, P, nullptr, H2DIM, 3 * H2DIM, H2DIM, 3 * H2DIM, H2DIM, H2DIM, 0, 0);

    tlogits_kernel<<<NN, 320>>>(templates);
    betas_kernel<<<TDIM, 256>>>();
    embs_part_kernel<<<dim3(H2DIM / 128, NSPLIT), 128>>>();
    embs_reduce_kernel<<<(TDIM * H2DIM + 255) / 256, 256>>>();
    glob1_kernel<<<dim3(16, TDIM), 256>>>(glob_w1, glob_b1);
    final2_kernel<<<1, 256>>>(glob_w2, glob_b2, cls_w, cls_b, out, out_size);
}